// round 1
// baseline (speedup 1.0000x reference)
#include <cuda_runtime.h>
#include <math.h>

#define NN 50000
#define NE 800000
#define NG 128
#define DIM 128
#define NCLS 10

// Scratch (static device globals: allowed; no runtime allocation)
__device__ float g_bufA[NN * DIM];
__device__ float g_bufB[NN * DIM];
__device__ float g_msg[NN * DIM];
__device__ float g_acc[NN * DIM];
__device__ float g_invdeg[NN];

// ---------------- utility kernels ----------------

__global__ void zero_f4(float4* p, int n4) {
    int i = blockIdx.x * blockDim.x + threadIdx.x;
    if (i < n4) p[i] = make_float4(0.f, 0.f, 0.f, 0.f);
}

__global__ void deg_kernel(const int* __restrict__ dst, float* __restrict__ deg) {
    int e = blockIdx.x * blockDim.x + threadIdx.x;
    if (e < NE) atomicAdd(&deg[dst[e]], 1.0f);
}

__global__ void finalize_invdeg(float* p) {
    int i = blockIdx.x * blockDim.x + threadIdx.x;
    if (i < NN) p[i] = 1.0f / fmaxf(p[i], 1.0f);
}

// ---------------- GEMM: C[N,128] = A[N,128] @ W[128,128], optional fused SAGE epilogue ----------------
// Block: 256 threads = 8 row-groups (warps) x 32 col-groups. Each thread: 8 rows x 4 cols.
// A-row loads are warp-uniform (broadcast). W served from L1/L2 (64 KB).
template <bool EPI>
__global__ void __launch_bounds__(256, 2)
gemm128(const float* __restrict__ A, const float* __restrict__ W,
        float* __restrict__ C,
        const float* __restrict__ acc, const float* __restrict__ invdeg,
        const float* __restrict__ bias) {
    const int rg = threadIdx.x >> 5;   // 0..7  (warp id)
    const int cg = threadIdx.x & 31;   // 0..31 (lane)
    const int row0 = blockIdx.x * 64 + rg * 8;
    const int col0 = cg * 4;

    float c[8][4];
#pragma unroll
    for (int i = 0; i < 8; ++i)
#pragma unroll
        for (int j = 0; j < 4; ++j) c[i][j] = 0.f;

    for (int k = 0; k < DIM; k += 4) {
        float bk[4][4];
#pragma unroll
        for (int kk = 0; kk < 4; ++kk) {
            float4 t = *(const float4*)(W + (k + kk) * DIM + col0);
            bk[kk][0] = t.x; bk[kk][1] = t.y; bk[kk][2] = t.z; bk[kk][3] = t.w;
        }
#pragma unroll
        for (int i = 0; i < 8; ++i) {
            int r = row0 + i;
            float av[4];
            if (r < NN) {
                float4 a = *(const float4*)(A + r * DIM + k);
                av[0] = a.x; av[1] = a.y; av[2] = a.z; av[3] = a.w;
            } else {
                av[0] = av[1] = av[2] = av[3] = 0.f;
            }
#pragma unroll
            for (int kk = 0; kk < 4; ++kk)
#pragma unroll
                for (int j = 0; j < 4; ++j)
                    c[i][j] = fmaf(av[kk], bk[kk][j], c[i][j]);
        }
    }

    float bv[4] = {0.f, 0.f, 0.f, 0.f};
    if (EPI) {
        float4 bb = *(const float4*)(bias + col0);
        bv[0] = bb.x; bv[1] = bb.y; bv[2] = bb.z; bv[3] = bb.w;
    }

#pragma unroll
    for (int i = 0; i < 8; ++i) {
        int r = row0 + i;
        if (r >= NN) continue;
        float4 o;
        if (EPI) {
            float id = invdeg[r];
            float4 ac = *(const float4*)(acc + r * DIM + col0);
            o.x = fmaxf(fmaf(ac.x, id, c[i][0] + bv[0]), 0.f);
            o.y = fmaxf(fmaf(ac.y, id, c[i][1] + bv[1]), 0.f);
            o.z = fmaxf(fmaf(ac.z, id, c[i][2] + bv[2]), 0.f);
            o.w = fmaxf(fmaf(ac.w, id, c[i][3] + bv[3]), 0.f);
        } else {
            o.x = c[i][0]; o.y = c[i][1]; o.z = c[i][2]; o.w = c[i][3];
        }
        *(float4*)(C + r * DIM + col0) = o;
    }
}

// ---------------- edge scatter: acc[dst] += g[src], one warp per edge ----------------
__global__ void __launch_bounds__(256)
scatter_kernel(const float* __restrict__ g, const int* __restrict__ src,
               const int* __restrict__ dst, float* __restrict__ acc) {
    long long idx = (long long)blockIdx.x * blockDim.x + threadIdx.x;
    int e = (int)(idx >> 5);
    int lane = (int)(idx & 31);
    if (e >= NE) return;
    int s = __ldg(&src[e]);
    int d = __ldg(&dst[e]);
    float4 v = *(const float4*)(g + (long long)s * DIM + lane * 4);
    float* p = acc + (long long)d * DIM + lane * 4;
    asm volatile("red.global.add.v4.f32 [%0], {%1, %2, %3, %4};"
                 :: "l"(p), "f"(v.x), "f"(v.y), "f"(v.z), "f"(v.w)
                 : "memory");
}

// ---------------- mean graph pooling + classifier head ----------------
__global__ void __launch_bounds__(128)
pool_kernel(const float* __restrict__ h, const int* __restrict__ gids,
            const float* __restrict__ Wf, const float* __restrict__ bf,
            float* __restrict__ out) {
    __shared__ float pooled[DIM];
    int g = blockIdx.x;
    int t = threadIdx.x;

    // graph_ids sorted: binary search segment [start, end)
    int lo = 0, hi = NN;
    while (lo < hi) { int m = (lo + hi) >> 1; if (gids[m] < g) lo = m + 1; else hi = m; }
    int start = lo;
    lo = start; hi = NN;
    while (lo < hi) { int m = (lo + hi) >> 1; if (gids[m] < g + 1) lo = m + 1; else hi = m; }
    int end = lo;

    float s = 0.f;
    for (int n = start; n < end; ++n) s += h[(long long)n * DIM + t];
    float cnt = fmaxf((float)(end - start), 1.0f);
    pooled[t] = s / cnt;
    __syncthreads();

    if (t < NCLS) {
        float o = bf[t];
#pragma unroll 8
        for (int k = 0; k < DIM; ++k) o = fmaf(pooled[k], Wf[k * NCLS + t], o);
        out[g * NCLS + t] = o;
    }
}

// ---------------- launch ----------------
extern "C" void kernel_launch(void* const* d_in, const int* in_sizes, int n_in,
                              void* d_out, int out_size) {
    const float* feat = (const float*)d_in[0];
    const int* esrc = (const int*)d_in[1];
    const int* edst = (const int*)d_in[2];
    const int* gids = (const int*)d_in[3];
    const float* Ws[3] = {(const float*)d_in[4], (const float*)d_in[7], (const float*)d_in[10]};
    const float* Wn[3] = {(const float*)d_in[5], (const float*)d_in[8], (const float*)d_in[11]};
    const float* bs[3] = {(const float*)d_in[6], (const float*)d_in[9], (const float*)d_in[12]};
    const float* Wf = (const float*)d_in[13];
    const float* bf = (const float*)d_in[14];
    float* out = (float*)d_out;

    float *bufA, *bufB, *msg, *acc, *invdeg;
    cudaGetSymbolAddress((void**)&bufA, g_bufA);
    cudaGetSymbolAddress((void**)&bufB, g_bufB);
    cudaGetSymbolAddress((void**)&msg, g_msg);
    cudaGetSymbolAddress((void**)&acc, g_acc);
    cudaGetSymbolAddress((void**)&invdeg, g_invdeg);

    // degrees -> inv_deg
    zero_f4<<<(NN / 4 + 255) / 256, 256>>>((float4*)invdeg, NN / 4);
    deg_kernel<<<(NE + 255) / 256, 256>>>(edst, invdeg);
    finalize_invdeg<<<(NN + 255) / 256, 256>>>(invdeg);

    const int gemm_blocks = (NN + 63) / 64;
    const int scat_blocks = (int)(((long long)NE * 32 + 255) / 256);
    const int zero_blocks = (NN * DIM / 4 + 255) / 256;

    const float* h = feat;
    float* outbuf = bufA;
    for (int l = 0; l < 3; ++l) {
        gemm128<false><<<gemm_blocks, 256>>>(h, Wn[l], msg, nullptr, nullptr, nullptr);
        zero_f4<<<zero_blocks, 256>>>((float4*)acc, NN * DIM / 4);
        scatter_kernel<<<scat_blocks, 256>>>(msg, esrc, edst, acc);
        gemm128<true><<<gemm_blocks, 256>>>(h, Ws[l], outbuf, acc, invdeg, bs[l]);
        h = outbuf;
        outbuf = (outbuf == bufA) ? bufB : bufA;
    }

    pool_kernel<<<NG, 128>>>(h, gids, Wf, bf, out);
}

// round 3
// speedup vs baseline: 1.9034x; 1.9034x over previous
#include <cuda_runtime.h>
#include <cuda_bf16.h>
#include <cstdint>
#include <math.h>

#define NN 50000
#define NE 800000
#define NG 128
#define DIM 128
#define NCLS 10

// ---------------- device scratch (static globals; no runtime alloc) ----------------
__device__ float g_bufA[NN * DIM];
__device__ float g_bufB[NN * DIM];
__device__ float g_acc[NN * DIM];
__device__ float g_invdeg[NN];
__device__ int g_deg[NN];
__device__ int g_rowptr[NN + 1];
__device__ int g_cursor[NN];
__device__ int g_csr[NE];
// Transposed+concatenated weights, bf16 split hi/lo: [layer][n=128][k=256]
__device__ __nv_bfloat16 g_Bth[3 * DIM * 2 * DIM];
__device__ __nv_bfloat16 g_Btl[3 * DIM * 2 * DIM];

// ---------------- helpers ----------------
__device__ __forceinline__ uint32_t smem_u32(const void* p) {
    return (uint32_t)__cvta_generic_to_shared((void*)p);
}
__device__ __forceinline__ uint32_t swz(uint32_t x) { return x ^ ((x >> 3) & 0x70); }

__device__ __forceinline__ void split_bf16(float x, __nv_bfloat16& hi, __nv_bfloat16& lo) {
    hi = __float2bfloat16(x);
    lo = __float2bfloat16(x - __bfloat162float(hi));
}
__device__ __forceinline__ uint32_t pack2(__nv_bfloat16 a, __nv_bfloat16 b) {
    __nv_bfloat162 t;
    t.x = a; t.y = b;
    return *(uint32_t*)&t;
}

__device__ __forceinline__ void ldmx4(uint32_t* r, uint32_t a) {
    asm volatile("ldmatrix.sync.aligned.m8n8.x4.shared.b16 {%0,%1,%2,%3}, [%4];"
                 : "=r"(r[0]), "=r"(r[1]), "=r"(r[2]), "=r"(r[3]) : "r"(a));
}
__device__ __forceinline__ void mma16816(float* c, const uint32_t* a, uint32_t b0,
                                         uint32_t b1) {
    asm volatile(
        "mma.sync.aligned.m16n8k16.row.col.f32.bf16.bf16.f32 "
        "{%0,%1,%2,%3}, {%4,%5,%6,%7}, {%8,%9}, {%0,%1,%2,%3};"
        : "+f"(c[0]), "+f"(c[1]), "+f"(c[2]), "+f"(c[3])
        : "r"(a[0]), "r"(a[1]), "r"(a[2]), "r"(a[3]), "r"(b0), "r"(b1));
}

// ---------------- CSR build ----------------
__global__ void zero_int(int* p, int n) {
    int i = blockIdx.x * blockDim.x + threadIdx.x;
    if (i < n) p[i] = 0;
}
__global__ void hist_kernel(const int* __restrict__ dst, int* __restrict__ deg) {
    int e = blockIdx.x * blockDim.x + threadIdx.x;
    if (e < NE) atomicAdd(&deg[dst[e]], 1);
}
// single-block exclusive scan over degrees -> rowptr, cursor, invdeg
__global__ void __launch_bounds__(1024)
scan_kernel(const int* __restrict__ deg, int* __restrict__ rowptr,
            int* __restrict__ cursor, float* __restrict__ invdeg) {
    __shared__ int ssum[1024];
    const int t = threadIdx.x;
    const int CH = (NN + 1023) / 1024;  // 49
    const int base = t * CH;
    int s = 0;
    for (int i = 0; i < CH; ++i) {
        int idx = base + i;
        if (idx < NN) s += deg[idx];
    }
    ssum[t] = s;
    __syncthreads();
    for (int off = 1; off < 1024; off <<= 1) {
        int v = (t >= off) ? ssum[t - off] : 0;
        __syncthreads();
        ssum[t] += v;
        __syncthreads();
    }
    int run = ssum[t] - s;  // exclusive prefix of this chunk
    for (int i = 0; i < CH; ++i) {
        int idx = base + i;
        if (idx < NN) {
            int d = deg[idx];
            rowptr[idx] = run;
            cursor[idx] = run;
            invdeg[idx] = 1.0f / fmaxf((float)d, 1.0f);
            run += d;
        }
    }
    if (t == 1023) rowptr[NN] = NE;
}
__global__ void fill_kernel(const int* __restrict__ src, const int* __restrict__ dst,
                            int* __restrict__ cursor, int* __restrict__ csr) {
    int e = blockIdx.x * blockDim.x + threadIdx.x;
    if (e >= NE) return;
    int d = dst[e];
    int pos = atomicAdd(&cursor[d], 1);
    csr[pos] = src[e];
}

// ---------------- weight prep: transpose+concat, bf16 hi/lo split ----------------
__global__ void prep_w(const float* __restrict__ Ws, const float* __restrict__ Wn,
                       __nv_bfloat16* __restrict__ Bth, __nv_bfloat16* __restrict__ Btl) {
    int i = blockIdx.x * blockDim.x + threadIdx.x;
    if (i >= DIM * 2 * DIM) return;
    int n = i >> 8;
    int k = i & 255;
    float w = (k < DIM) ? Ws[k * DIM + n] : Wn[(k - DIM) * DIM + n];
    __nv_bfloat16 hi, lo;
    split_bf16(w, hi, lo);
    Bth[i] = hi;
    Btl[i] = lo;
}

// ---------------- CSR gather: acc[n] = mean over in-neighbors of h[src] ----------------
__global__ void __launch_bounds__(256)
gather_kernel(const float* __restrict__ h, const int* __restrict__ rowptr,
              const int* __restrict__ csr, const float* __restrict__ invdeg,
              float* __restrict__ acc) {
    int node = blockIdx.x * 8 + (threadIdx.x >> 5);
    int lane = threadIdx.x & 31;
    if (node >= NN) return;
    int beg = __ldg(&rowptr[node]);
    int end = __ldg(&rowptr[node + 1]);
    float4 s = make_float4(0.f, 0.f, 0.f, 0.f);
#pragma unroll 2
    for (int i = beg; i < end; ++i) {
        int sc = __ldg(&csr[i]);
        float4 v = *(const float4*)(h + (size_t)sc * DIM + lane * 4);
        s.x += v.x; s.y += v.y; s.z += v.z; s.w += v.w;
    }
    float id = invdeg[node];
    s.x *= id; s.y *= id; s.z *= id; s.w *= id;
    *(float4*)(acc + (size_t)node * DIM + lane * 4) = s;
}

// ---------------- fused SAGE GEMM: relu([h|acc][M,256] @ Bt^T + bias) ----------------
// mma.sync m16n8k16 bf16, 3-term split. CTA 128x128 tile, 8 warps (4M x 2N).
#define SMA_HI 0
#define SMA_LO 16384
#define SMB_HI 32768
#define SMB_LO 49152
#define SMEM_BYTES 65536

__global__ void __launch_bounds__(256, 1)
sage_gemm(const float* __restrict__ h, const float* __restrict__ acc,
          const __nv_bfloat16* __restrict__ Bth, const __nv_bfloat16* __restrict__ Btl,
          const float* __restrict__ bias, float* __restrict__ out) {
    extern __shared__ char sm[];
    const uint32_t sb = smem_u32(sm);
    const int t = threadIdx.x;
    const int lane = t & 31;
    const int wid = t >> 5;
    const int wm = wid & 3;   // M warp: 32 rows
    const int wn = wid >> 2;  // N warp: 64 cols
    const int row0 = blockIdx.x * 128;

    float cacc[2][8][4];
#pragma unroll
    for (int a = 0; a < 2; ++a)
#pragma unroll
        for (int b = 0; b < 8; ++b)
#pragma unroll
            for (int c = 0; c < 4; ++c) cacc[a][b][c] = 0.f;

    for (int kc = 0; kc < 4; ++kc) {  // K chunks of 64
        const float* Asrc = (kc < 2) ? h : acc;
        const int kbase = (kc & 1) * 64;

        // stage A chunk: 128 rows x 64 cols fp32 -> bf16 hi/lo, SW128 swizzled
#pragma unroll
        for (int u = 0; u < 8; ++u) {
            int li = t + 256 * u;      // 0..2047
            int row = li >> 4;         // 16 float4 per row
            int c4 = li & 15;
            int r = row0 + row;
            float4 v = make_float4(0.f, 0.f, 0.f, 0.f);
            if (r < NN) v = *(const float4*)(Asrc + (size_t)r * DIM + kbase + c4 * 4);
            __nv_bfloat16 h0, h1, h2, h3, l0, l1, l2, l3;
            split_bf16(v.x, h0, l0);
            split_bf16(v.y, h1, l1);
            split_bf16(v.z, h2, l2);
            split_bf16(v.w, h3, l3);
            uint32_t off = swz((uint32_t)(row * 128 + c4 * 8));
            *(uint2*)(sm + SMA_HI + off) = make_uint2(pack2(h0, h1), pack2(h2, h3));
            *(uint2*)(sm + SMA_LO + off) = make_uint2(pack2(l0, l1), pack2(l2, l3));
        }
        // stage B chunk: 128 n-rows x 64 k (prepacked bf16 hi/lo)
#pragma unroll
        for (int u = 0; u < 4; ++u) {
            int li = t + 256 * u;      // 0..1023
            int nrow = li >> 3;        // 8 uint4 per row
            int c16 = li & 7;
            size_t gb = (size_t)nrow * 256 + kc * 64 + c16 * 8;  // bf16 elems
            uint4 vh = *(const uint4*)(Bth + gb);
            uint4 vl = *(const uint4*)(Btl + gb);
            uint32_t off = swz((uint32_t)(nrow * 128 + c16 * 16));
            *(uint4*)(sm + SMB_HI + off) = vh;
            *(uint4*)(sm + SMB_LO + off) = vl;
        }
        __syncthreads();

#pragma unroll
        for (int ks = 0; ks < 4; ++ks) {  // k16 steps within chunk
            uint32_t ahi[2][4], alo[2][4];
#pragma unroll
            for (int mt = 0; mt < 2; ++mt) {
                uint32_t row = wm * 32 + mt * 16 + (lane & 7) + ((lane >> 3) & 1) * 8;
                uint32_t cb = ks * 32 + ((lane >> 4) & 1) * 16;
                uint32_t o = swz(row * 128 + cb);
                ldmx4(ahi[mt], sb + SMA_HI + o);
                ldmx4(alo[mt], sb + SMA_LO + o);
            }
#pragma unroll
            for (int np = 0; np < 4; ++np) {  // pairs of n8 tiles
                uint32_t nrow = wn * 64 + np * 16 + (lane & 7) + ((lane >> 4) & 1) * 8;
                uint32_t cb = ks * 32 + ((lane >> 3) & 1) * 16;
                uint32_t o = swz(nrow * 128 + cb);
                uint32_t bh[4], bl[4];
                ldmx4(bh, sb + SMB_HI + o);
                ldmx4(bl, sb + SMB_LO + o);
#pragma unroll
                for (int mt = 0; mt < 2; ++mt) {
                    mma16816(cacc[mt][2 * np], ahi[mt], bh[0], bh[1]);
                    mma16816(cacc[mt][2 * np], ahi[mt], bl[0], bl[1]);
                    mma16816(cacc[mt][2 * np], alo[mt], bh[0], bh[1]);
                    mma16816(cacc[mt][2 * np + 1], ahi[mt], bh[2], bh[3]);
                    mma16816(cacc[mt][2 * np + 1], ahi[mt], bl[2], bl[3]);
                    mma16816(cacc[mt][2 * np + 1], alo[mt], bh[2], bh[3]);
                }
            }
        }
        __syncthreads();
    }

    // epilogue: +bias, relu, store
#pragma unroll
    for (int mt = 0; mt < 2; ++mt) {
        int r0 = row0 + wm * 32 + mt * 16 + (lane >> 2);
#pragma unroll
        for (int nt = 0; nt < 8; ++nt) {
            int c = wn * 64 + nt * 8 + (lane & 3) * 2;
            float b0 = __ldg(&bias[c]);
            float b1 = __ldg(&bias[c + 1]);
            float* cc = cacc[mt][nt];
            if (r0 < NN) {
                float2 v = make_float2(fmaxf(cc[0] + b0, 0.f), fmaxf(cc[1] + b1, 0.f));
                *(float2*)(out + (size_t)r0 * DIM + c) = v;
            }
            int r1 = r0 + 8;
            if (r1 < NN) {
                float2 v = make_float2(fmaxf(cc[2] + b0, 0.f), fmaxf(cc[3] + b1, 0.f));
                *(float2*)(out + (size_t)r1 * DIM + c) = v;
            }
        }
    }
}

// ---------------- mean graph pooling + classifier head ----------------
__global__ void __launch_bounds__(128)
pool_kernel(const float* __restrict__ h, const int* __restrict__ gids,
            const float* __restrict__ Wf, const float* __restrict__ bf,
            float* __restrict__ out) {
    __shared__ float pooled[DIM];
    int g = blockIdx.x;
    int t = threadIdx.x;

    int lo = 0, hi = NN;
    while (lo < hi) { int m = (lo + hi) >> 1; if (gids[m] < g) lo = m + 1; else hi = m; }
    int start = lo;
    lo = start; hi = NN;
    while (lo < hi) { int m = (lo + hi) >> 1; if (gids[m] < g + 1) lo = m + 1; else hi = m; }
    int end = lo;

    float s = 0.f;
    for (int n = start; n < end; ++n) s += h[(size_t)n * DIM + t];
    float cnt = fmaxf((float)(end - start), 1.0f);
    pooled[t] = s / cnt;
    __syncthreads();

    if (t < NCLS) {
        float o = bf[t];
#pragma unroll 8
        for (int k = 0; k < DIM; ++k) o = fmaf(pooled[k], Wf[k * NCLS + t], o);
        out[g * NCLS + t] = o;
    }
}

// ---------------- launch ----------------
extern "C" void kernel_launch(void* const* d_in, const int* in_sizes, int n_in,
                              void* d_out, int out_size) {
    const float* feat = (const float*)d_in[0];
    const int* esrc = (const int*)d_in[1];
    const int* edst = (const int*)d_in[2];
    const int* gids = (const int*)d_in[3];
    const float* Ws[3] = {(const float*)d_in[4], (const float*)d_in[7], (const float*)d_in[10]};
    const float* Wn[3] = {(const float*)d_in[5], (const float*)d_in[8], (const float*)d_in[11]};
    const float* bs[3] = {(const float*)d_in[6], (const float*)d_in[9], (const float*)d_in[12]};
    const float* Wf = (const float*)d_in[13];
    const float* bf = (const float*)d_in[14];
    float* out = (float*)d_out;

    float *bufA, *bufB, *acc, *invdeg;
    int *deg, *rowptr, *cursor, *csr;
    __nv_bfloat16 *Bth, *Btl;
    cudaGetSymbolAddress((void**)&bufA, g_bufA);
    cudaGetSymbolAddress((void**)&bufB, g_bufB);
    cudaGetSymbolAddress((void**)&acc, g_acc);
    cudaGetSymbolAddress((void**)&invdeg, g_invdeg);
    cudaGetSymbolAddress((void**)&deg, g_deg);
    cudaGetSymbolAddress((void**)&rowptr, g_rowptr);
    cudaGetSymbolAddress((void**)&cursor, g_cursor);
    cudaGetSymbolAddress((void**)&csr, g_csr);
    cudaGetSymbolAddress((void**)&Bth, g_Bth);
    cudaGetSymbolAddress((void**)&Btl, g_Btl);

    cudaFuncSetAttribute(sage_gemm, cudaFuncAttributeMaxDynamicSharedMemorySize, SMEM_BYTES);

    // CSR build + invdeg
    zero_int<<<(NN + 255) / 256, 256>>>(deg, NN);
    hist_kernel<<<(NE + 255) / 256, 256>>>(edst, deg);
    scan_kernel<<<1, 1024>>>(deg, rowptr, cursor, invdeg);
    fill_kernel<<<(NE + 255) / 256, 256>>>(esrc, edst, cursor, csr);

    // weight prep
    const int wprep_blocks = (DIM * 2 * DIM + 255) / 256;
    for (int l = 0; l < 3; ++l)
        prep_w<<<wprep_blocks, 256>>>(Ws[l], Wn[l], Bth + l * DIM * 2 * DIM,
                                      Btl + l * DIM * 2 * DIM);

    const int gemm_blocks = (NN + 127) / 128;
    const int gather_blocks = (NN + 7) / 8;

    const float* h = feat;
    float* outbuf = bufA;
    for (int l = 0; l < 3; ++l) {
        gather_kernel<<<gather_blocks, 256>>>(h, rowptr, csr, invdeg, acc);
        sage_gemm<<<gemm_blocks, 256, SMEM_BYTES>>>(h, acc,
                                                    Bth + l * DIM * 2 * DIM,
                                                    Btl + l * DIM * 2 * DIM,
                                                    bs[l], outbuf);
        h = outbuf;
        outbuf = (outbuf == bufA) ? bufB : bufA;
    }

    pool_kernel<<<NG, 128>>>(h, gids, Wf, bf, out);
}

// round 4
// speedup vs baseline: 1.9489x; 1.0239x over previous
#include <cuda_runtime.h>
#include <cuda_bf16.h>
#include <cuda_fp16.h>
#include <cstdint>
#include <math.h>

#define NN 50000
#define NE 800000
#define NG 128
#define DIM 128
#define NCLS 10

// ---------------- device scratch (static globals; no runtime alloc) ----------------
__device__ float g_bufA[NN * DIM];
__device__ float g_bufB[NN * DIM];
__device__ float g_acc[NN * DIM];
__device__ float g_invdeg[NN];
__device__ __half g_h16[NN * DIM];
__device__ int g_deg[NN];
__device__ int g_rowptr[NN + 1];
__device__ int g_cursor[NN];
__device__ int g_csr[NE];
// Transposed+concatenated weights, bf16 split hi/lo: [layer][n=128][k=256]
__device__ __nv_bfloat16 g_Bth[3 * DIM * 2 * DIM];
__device__ __nv_bfloat16 g_Btl[3 * DIM * 2 * DIM];

// ---------------- helpers ----------------
__device__ __forceinline__ uint32_t smem_u32(const void* p) {
    return (uint32_t)__cvta_generic_to_shared((void*)p);
}
__device__ __forceinline__ uint32_t swz(uint32_t x) { return x ^ ((x >> 3) & 0x70); }

__device__ __forceinline__ void split_bf16(float x, __nv_bfloat16& hi, __nv_bfloat16& lo) {
    hi = __float2bfloat16(x);
    lo = __float2bfloat16(x - __bfloat162float(hi));
}
__device__ __forceinline__ uint32_t pack2(__nv_bfloat16 a, __nv_bfloat16 b) {
    __nv_bfloat162 t;
    t.x = a; t.y = b;
    return *(uint32_t*)&t;
}

__device__ __forceinline__ void ldmx4(uint32_t* r, uint32_t a) {
    asm volatile("ldmatrix.sync.aligned.m8n8.x4.shared.b16 {%0,%1,%2,%3}, [%4];"
                 : "=r"(r[0]), "=r"(r[1]), "=r"(r[2]), "=r"(r[3]) : "r"(a));
}
__device__ __forceinline__ void mma16816(float* c, const uint32_t* a, uint32_t b0,
                                         uint32_t b1) {
    asm volatile(
        "mma.sync.aligned.m16n8k16.row.col.f32.bf16.bf16.f32 "
        "{%0,%1,%2,%3}, {%4,%5,%6,%7}, {%8,%9}, {%0,%1,%2,%3};"
        : "+f"(c[0]), "+f"(c[1]), "+f"(c[2]), "+f"(c[3])
        : "r"(a[0]), "r"(a[1]), "r"(a[2]), "r"(a[3]), "r"(b0), "r"(b1));
}

// ---------------- CSR build ----------------
__global__ void zero_int(int* p, int n) {
    int i = blockIdx.x * blockDim.x + threadIdx.x;
    if (i < n) p[i] = 0;
}
__global__ void hist_kernel(const int* __restrict__ dst, int* __restrict__ deg) {
    int e = blockIdx.x * blockDim.x + threadIdx.x;
    if (e < NE) atomicAdd(&deg[dst[e]], 1);
}
__global__ void __launch_bounds__(1024)
scan_kernel(const int* __restrict__ deg, int* __restrict__ rowptr,
            int* __restrict__ cursor, float* __restrict__ invdeg) {
    __shared__ int ssum[1024];
    const int t = threadIdx.x;
    const int CH = (NN + 1023) / 1024;  // 49
    const int base = t * CH;
    int s = 0;
    for (int i = 0; i < CH; ++i) {
        int idx = base + i;
        if (idx < NN) s += deg[idx];
    }
    ssum[t] = s;
    __syncthreads();
    for (int off = 1; off < 1024; off <<= 1) {
        int v = (t >= off) ? ssum[t - off] : 0;
        __syncthreads();
        ssum[t] += v;
        __syncthreads();
    }
    int run = ssum[t] - s;
    for (int i = 0; i < CH; ++i) {
        int idx = base + i;
        if (idx < NN) {
            int d = deg[idx];
            rowptr[idx] = run;
            cursor[idx] = run;
            invdeg[idx] = 1.0f / fmaxf((float)d, 1.0f);
            run += d;
        }
    }
    if (t == 1023) rowptr[NN] = NE;
}
__global__ void fill_kernel(const int* __restrict__ src, const int* __restrict__ dst,
                            int* __restrict__ cursor, int* __restrict__ csr) {
    int e = blockIdx.x * blockDim.x + threadIdx.x;
    if (e >= NE) return;
    int d = dst[e];
    int pos = atomicAdd(&cursor[d], 1);
    csr[pos] = src[e];
}

// ---------------- weight prep ----------------
__global__ void prep_w(const float* __restrict__ Ws, const float* __restrict__ Wn,
                       __nv_bfloat16* __restrict__ Bth, __nv_bfloat16* __restrict__ Btl) {
    int i = blockIdx.x * blockDim.x + threadIdx.x;
    if (i >= DIM * 2 * DIM) return;
    int n = i >> 8;
    int k = i & 255;
    float w = (k < DIM) ? Ws[k * DIM + n] : Wn[(k - DIM) * DIM + n];
    __nv_bfloat16 hi, lo;
    split_bf16(w, hi, lo);
    Bth[i] = hi;
    Btl[i] = lo;
}

// ---------------- features -> fp16 copy (for layer-0 gather) ----------------
__global__ void feat_to_h16(const float* __restrict__ f, __half* __restrict__ o) {
    int i = blockIdx.x * blockDim.x + threadIdx.x;  // 8 elems each
    if (i >= NN * DIM / 8) return;
    const float4* p = (const float4*)f + (size_t)i * 2;
    float4 a = p[0], b = p[1];
    uint4 v;
    __half2 t0 = __floats2half2_rn(a.x, a.y);
    __half2 t1 = __floats2half2_rn(a.z, a.w);
    __half2 t2 = __floats2half2_rn(b.x, b.y);
    __half2 t3 = __floats2half2_rn(b.z, b.w);
    v.x = *(uint32_t*)&t0; v.y = *(uint32_t*)&t1;
    v.z = *(uint32_t*)&t2; v.w = *(uint32_t*)&t3;
    *((uint4*)o + i) = v;
}

// ---------------- CSR gather (fp16 input): acc[n] = mean_{src in N(n)} h16[src] ----------------
__global__ void __launch_bounds__(256)
gather16_kernel(const __half* __restrict__ h16, const int* __restrict__ rowptr,
                const int* __restrict__ csr, const float* __restrict__ invdeg,
                float* __restrict__ acc) {
    int node = blockIdx.x * 8 + (threadIdx.x >> 5);
    int lane = threadIdx.x & 31;
    if (node >= NN) return;
    int beg = __ldg(&rowptr[node]);
    int end = __ldg(&rowptr[node + 1]);
    float s0 = 0.f, s1 = 0.f, s2 = 0.f, s3 = 0.f;
    int i = beg;
    for (; i + 3 < end; i += 4) {
        int n0 = __ldg(&csr[i]), n1 = __ldg(&csr[i + 1]);
        int n2 = __ldg(&csr[i + 2]), n3 = __ldg(&csr[i + 3]);
        uint2 v0 = *(const uint2*)(h16 + (size_t)n0 * DIM + lane * 4);
        uint2 v1 = *(const uint2*)(h16 + (size_t)n1 * DIM + lane * 4);
        uint2 v2 = *(const uint2*)(h16 + (size_t)n2 * DIM + lane * 4);
        uint2 v3 = *(const uint2*)(h16 + (size_t)n3 * DIM + lane * 4);
#define ACC8(v)                                                     \
        {                                                           \
            float2 fa = __half22float2(*(__half2*)&(v).x);          \
            float2 fb = __half22float2(*(__half2*)&(v).y);          \
            s0 += fa.x; s1 += fa.y; s2 += fb.x; s3 += fb.y;         \
        }
        ACC8(v0) ACC8(v1) ACC8(v2) ACC8(v3)
    }
    for (; i < end; ++i) {
        int n0 = __ldg(&csr[i]);
        uint2 v0 = *(const uint2*)(h16 + (size_t)n0 * DIM + lane * 4);
        ACC8(v0)
    }
#undef ACC8
    float id = invdeg[node];
    float4 o = make_float4(s0 * id, s1 * id, s2 * id, s3 * id);
    *(float4*)(acc + (size_t)node * DIM + lane * 4) = o;
}

// ---------------- fused SAGE GEMM: relu([h|acc][M,256] @ Bt^T + bias) ----------------
#define SMA_HI 0
#define SMA_LO 16384
#define SMB_HI 32768
#define SMB_LO 49152
#define SMEM_BYTES 65536

__global__ void __launch_bounds__(256, 1)
sage_gemm(const float* __restrict__ h, const float* __restrict__ acc,
          const __nv_bfloat16* __restrict__ Bth, const __nv_bfloat16* __restrict__ Btl,
          const float* __restrict__ bias, float* __restrict__ out,
          __half* __restrict__ out16) {
    extern __shared__ char sm[];
    const uint32_t sb = smem_u32(sm);
    const int t = threadIdx.x;
    const int lane = t & 31;
    const int wid = t >> 5;
    const int wm = wid & 3;
    const int wn = wid >> 2;
    const int row0 = blockIdx.x * 128;

    float cacc[2][8][4];
#pragma unroll
    for (int a = 0; a < 2; ++a)
#pragma unroll
        for (int b = 0; b < 8; ++b)
#pragma unroll
            for (int c = 0; c < 4; ++c) cacc[a][b][c] = 0.f;

    float4 pref[8];
    // prefetch A chunk 0
    {
        const float* Asrc = h;
#pragma unroll
        for (int u = 0; u < 8; ++u) {
            int li = t + 256 * u;
            int row = li >> 4, c4 = li & 15;
            int r = row0 + row;
            pref[u] = (r < NN) ? *(const float4*)(Asrc + (size_t)r * DIM + c4 * 4)
                               : make_float4(0.f, 0.f, 0.f, 0.f);
        }
    }

    for (int kc = 0; kc < 4; ++kc) {
        // ---- STS A chunk kc from pref regs (split to bf16 hi/lo) ----
#pragma unroll
        for (int u = 0; u < 8; ++u) {
            int li = t + 256 * u;
            int row = li >> 4, c4 = li & 15;
            float4 v = pref[u];
            __nv_bfloat16 h0, h1, h2, h3, l0, l1, l2, l3;
            split_bf16(v.x, h0, l0);
            split_bf16(v.y, h1, l1);
            split_bf16(v.z, h2, l2);
            split_bf16(v.w, h3, l3);
            uint32_t off = swz((uint32_t)(row * 128 + c4 * 8));
            *(uint2*)(sm + SMA_HI + off) = make_uint2(pack2(h0, h1), pack2(h2, h3));
            *(uint2*)(sm + SMA_LO + off) = make_uint2(pack2(l0, l1), pack2(l2, l3));
        }
        // ---- stage B chunk kc (L1/L2-hot) ----
#pragma unroll
        for (int u = 0; u < 4; ++u) {
            int li = t + 256 * u;
            int nrow = li >> 3;
            int c16 = li & 7;
            size_t gb = (size_t)nrow * 256 + kc * 64 + c16 * 8;
            uint4 vh = *(const uint4*)(Bth + gb);
            uint4 vl = *(const uint4*)(Btl + gb);
            uint32_t off = swz((uint32_t)(nrow * 128 + c16 * 16));
            *(uint4*)(sm + SMB_HI + off) = vh;
            *(uint4*)(sm + SMB_LO + off) = vl;
        }
        __syncthreads();

        // ---- prefetch A chunk kc+1 (hidden under MMA) ----
        if (kc < 3) {
            int knext = kc + 1;
            const float* Asrc = (knext < 2) ? h : acc;
            const int kbase = (knext & 1) * 64;
#pragma unroll
            for (int u = 0; u < 8; ++u) {
                int li = t + 256 * u;
                int row = li >> 4, c4 = li & 15;
                int r = row0 + row;
                pref[u] = (r < NN) ? *(const float4*)(Asrc + (size_t)r * DIM + kbase + c4 * 4)
                                   : make_float4(0.f, 0.f, 0.f, 0.f);
            }
        }

        // ---- MMA over smem chunk ----
#pragma unroll
        for (int ks = 0; ks < 4; ++ks) {
            uint32_t ahi[2][4], alo[2][4];
#pragma unroll
            for (int mt = 0; mt < 2; ++mt) {
                uint32_t row = wm * 32 + mt * 16 + (lane & 7) + ((lane >> 3) & 1) * 8;
                uint32_t cb = ks * 32 + ((lane >> 4) & 1) * 16;
                uint32_t o = swz(row * 128 + cb);
                ldmx4(ahi[mt], sb + SMA_HI + o);
                ldmx4(alo[mt], sb + SMA_LO + o);
            }
#pragma unroll
            for (int np = 0; np < 4; ++np) {
                uint32_t nrow = wn * 64 + np * 16 + (lane & 7) + ((lane >> 4) & 1) * 8;
                uint32_t cb = ks * 32 + ((lane >> 3) & 1) * 16;
                uint32_t o = swz(nrow * 128 + cb);
                uint32_t bh[4], bl[4];
                ldmx4(bh, sb + SMB_HI + o);
                ldmx4(bl, sb + SMB_LO + o);
#pragma unroll
                for (int mt = 0; mt < 2; ++mt) {
                    mma16816(cacc[mt][2 * np], ahi[mt], bh[0], bh[1]);
                    mma16816(cacc[mt][2 * np], ahi[mt], bl[0], bl[1]);
                    mma16816(cacc[mt][2 * np], alo[mt], bh[0], bh[1]);
                    mma16816(cacc[mt][2 * np + 1], ahi[mt], bh[2], bh[3]);
                    mma16816(cacc[mt][2 * np + 1], ahi[mt], bl[2], bl[3]);
                    mma16816(cacc[mt][2 * np + 1], alo[mt], bh[2], bh[3]);
                }
            }
        }
        __syncthreads();
    }

    // epilogue: +bias, relu, store fp32 + fp16
#pragma unroll
    for (int mt = 0; mt < 2; ++mt) {
        int r0 = row0 + wm * 32 + mt * 16 + (lane >> 2);
#pragma unroll
        for (int nt = 0; nt < 8; ++nt) {
            int c = wn * 64 + nt * 8 + (lane & 3) * 2;
            float b0 = __ldg(&bias[c]);
            float b1 = __ldg(&bias[c + 1]);
            float* cc = cacc[mt][nt];
            if (r0 < NN) {
                float2 v = make_float2(fmaxf(cc[0] + b0, 0.f), fmaxf(cc[1] + b1, 0.f));
                *(float2*)(out + (size_t)r0 * DIM + c) = v;
                __half2 hv = __floats2half2_rn(v.x, v.y);
                *(__half2*)(out16 + (size_t)r0 * DIM + c) = hv;
            }
            int r1 = r0 + 8;
            if (r1 < NN) {
                float2 v = make_float2(fmaxf(cc[2] + b0, 0.f), fmaxf(cc[3] + b1, 0.f));
                *(float2*)(out + (size_t)r1 * DIM + c) = v;
                __half2 hv = __floats2half2_rn(v.x, v.y);
                *(__half2*)(out16 + (size_t)r1 * DIM + c) = hv;
            }
        }
    }
}

// ---------------- mean graph pooling + classifier head ----------------
__global__ void __launch_bounds__(128)
pool_kernel(const float* __restrict__ h, const int* __restrict__ gids,
            const float* __restrict__ Wf, const float* __restrict__ bf,
            float* __restrict__ out) {
    __shared__ float pooled[DIM];
    int g = blockIdx.x;
    int t = threadIdx.x;

    int lo = 0, hi = NN;
    while (lo < hi) { int m = (lo + hi) >> 1; if (gids[m] < g) lo = m + 1; else hi = m; }
    int start = lo;
    lo = start; hi = NN;
    while (lo < hi) { int m = (lo + hi) >> 1; if (gids[m] < g + 1) lo = m + 1; else hi = m; }
    int end = lo;

    float s0 = 0.f, s1 = 0.f, s2 = 0.f, s3 = 0.f;
    int n = start;
    for (; n + 3 < end; n += 4) {
        s0 += h[(size_t)n * DIM + t];
        s1 += h[(size_t)(n + 1) * DIM + t];
        s2 += h[(size_t)(n + 2) * DIM + t];
        s3 += h[(size_t)(n + 3) * DIM + t];
    }
    for (; n < end; ++n) s0 += h[(size_t)n * DIM + t];
    float cnt = fmaxf((float)(end - start), 1.0f);
    pooled[t] = ((s0 + s1) + (s2 + s3)) / cnt;
    __syncthreads();

    if (t < NCLS) {
        float o = bf[t];
#pragma unroll 8
        for (int k = 0; k < DIM; ++k) o = fmaf(pooled[k], Wf[k * NCLS + t], o);
        out[g * NCLS + t] = o;
    }
}

// ---------------- launch ----------------
extern "C" void kernel_launch(void* const* d_in, const int* in_sizes, int n_in,
                              void* d_out, int out_size) {
    const float* feat = (const float*)d_in[0];
    const int* esrc = (const int*)d_in[1];
    const int* edst = (const int*)d_in[2];
    const int* gids = (const int*)d_in[3];
    const float* Ws[3] = {(const float*)d_in[4], (const float*)d_in[7], (const float*)d_in[10]};
    const float* Wn[3] = {(const float*)d_in[5], (const float*)d_in[8], (const float*)d_in[11]};
    const float* bs[3] = {(const float*)d_in[6], (const float*)d_in[9], (const float*)d_in[12]};
    const float* Wf = (const float*)d_in[13];
    const float* bf = (const float*)d_in[14];
    float* out = (float*)d_out;

    float *bufA, *bufB, *acc, *invdeg;
    __half* h16;
    int *deg, *rowptr, *cursor, *csr;
    __nv_bfloat16 *Bth, *Btl;
    cudaGetSymbolAddress((void**)&bufA, g_bufA);
    cudaGetSymbolAddress((void**)&bufB, g_bufB);
    cudaGetSymbolAddress((void**)&acc, g_acc);
    cudaGetSymbolAddress((void**)&invdeg, g_invdeg);
    cudaGetSymbolAddress((void**)&h16, g_h16);
    cudaGetSymbolAddress((void**)&deg, g_deg);
    cudaGetSymbolAddress((void**)&rowptr, g_rowptr);
    cudaGetSymbolAddress((void**)&cursor, g_cursor);
    cudaGetSymbolAddress((void**)&csr, g_csr);
    cudaGetSymbolAddress((void**)&Bth, g_Bth);
    cudaGetSymbolAddress((void**)&Btl, g_Btl);

    cudaFuncSetAttribute(sage_gemm, cudaFuncAttributeMaxDynamicSharedMemorySize, SMEM_BYTES);

    // CSR build + invdeg
    zero_int<<<(NN + 255) / 256, 256>>>(deg, NN);
    hist_kernel<<<(NE + 255) / 256, 256>>>(edst, deg);
    scan_kernel<<<1, 1024>>>(deg, rowptr, cursor, invdeg);
    fill_kernel<<<(NE + 255) / 256, 256>>>(esrc, edst, cursor, csr);

    // weight prep + fp16 features
    const int wprep_blocks = (DIM * 2 * DIM + 255) / 256;
    for (int l = 0; l < 3; ++l)
        prep_w<<<wprep_blocks, 256>>>(Ws[l], Wn[l], Bth + l * DIM * 2 * DIM,
                                      Btl + l * DIM * 2 * DIM);
    feat_to_h16<<<(NN * DIM / 8 + 255) / 256, 256>>>(feat, h16);

    const int gemm_blocks = (NN + 127) / 128;
    const int gather_blocks = (NN + 7) / 8;

    const float* h = feat;
    float* outbuf = bufA;
    for (int l = 0; l < 3; ++l) {
        gather16_kernel<<<gather_blocks, 256>>>(h16, rowptr, csr, invdeg, acc);
        sage_gemm<<<gemm_blocks, 256, SMEM_BYTES>>>(h, acc,
                                                    Bth + l * DIM * 2 * DIM,
                                                    Btl + l * DIM * 2 * DIM,
                                                    bs[l], outbuf, h16);
        h = outbuf;
        outbuf = (outbuf == bufA) ? bufB : bufA;
    }

    pool_kernel<<<NG, 128>>>(h, gids, Wf, bf, out);
}

// round 5
// speedup vs baseline: 2.4007x; 1.2318x over previous
#include <cuda_runtime.h>
#include <cuda_fp16.h>
#include <cstdint>
#include <math.h>

#define NN 50000
#define NE 800000
#define NG 128
#define DIM 128
#define NCLS 10

// ---------------- device scratch ----------------
__device__ __align__(16) __half g_hA[NN * DIM];
__device__ __align__(16) __half g_hB[NN * DIM];
__device__ __align__(16) __half g_acc16[NN * DIM];
__device__ float g_invdeg[NN];
__device__ int g_deg[NN];
__device__ int g_rowptr[NN + 1];
__device__ int g_cursor[NN];
__device__ int g_csr[NE];
// weights transposed+concat, fp16 hi/lo: [layer][n=128][k=256]
__device__ __align__(16) __half g_Bth[3 * DIM * 2 * DIM];
__device__ __align__(16) __half g_Btl[3 * DIM * 2 * DIM];

// ---------------- helpers ----------------
__device__ __forceinline__ uint32_t smem_u32(const void* p) {
    return (uint32_t)__cvta_generic_to_shared((void*)p);
}
__device__ __forceinline__ uint32_t swz(uint32_t x) { return x ^ ((x >> 3) & 0x70); }

__device__ __forceinline__ void cpa16(uint32_t dst, const void* src, int sz) {
    asm volatile("cp.async.cg.shared.global [%0], [%1], 16, %2;"
                 :: "r"(dst), "l"(src), "r"(sz) : "memory");
}
#define CP_COMMIT() asm volatile("cp.async.commit_group;" ::: "memory")
#define CP_WAIT(n) asm volatile("cp.async.wait_group %0;" :: "n"(n) : "memory")

__device__ __forceinline__ void ldmx4(uint32_t* r, uint32_t a) {
    asm volatile("ldmatrix.sync.aligned.m8n8.x4.shared.b16 {%0,%1,%2,%3}, [%4];"
                 : "=r"(r[0]), "=r"(r[1]), "=r"(r[2]), "=r"(r[3]) : "r"(a));
}
__device__ __forceinline__ void mma16816(float* c, const uint32_t* a, uint32_t b0,
                                         uint32_t b1) {
    asm volatile(
        "mma.sync.aligned.m16n8k16.row.col.f32.f16.f16.f32 "
        "{%0,%1,%2,%3}, {%4,%5,%6,%7}, {%8,%9}, {%0,%1,%2,%3};"
        : "+f"(c[0]), "+f"(c[1]), "+f"(c[2]), "+f"(c[3])
        : "r"(a[0]), "r"(a[1]), "r"(a[2]), "r"(a[3]), "r"(b0), "r"(b1));
}

// ---------------- CSR build ----------------
__global__ void zero_int(int* p, int n) {
    int i = blockIdx.x * blockDim.x + threadIdx.x;
    if (i < n) p[i] = 0;
}
__global__ void hist_kernel(const int* __restrict__ dst, int* __restrict__ deg) {
    int e0 = (blockIdx.x * blockDim.x + threadIdx.x) * 4;
#pragma unroll
    for (int i = 0; i < 4; ++i)
        if (e0 + i < NE) atomicAdd(&deg[__ldg(&dst[e0 + i])], 1);
}
__global__ void __launch_bounds__(1024)
scan_kernel(const int* __restrict__ deg, int* __restrict__ rowptr,
            int* __restrict__ cursor, float* __restrict__ invdeg) {
    __shared__ int ssum[1024];
    const int t = threadIdx.x;
    const int CH = (NN + 1023) / 1024;
    const int base = t * CH;
    int s = 0;
    for (int i = 0; i < CH; ++i) {
        int idx = base + i;
        if (idx < NN) s += deg[idx];
    }
    ssum[t] = s;
    __syncthreads();
    for (int off = 1; off < 1024; off <<= 1) {
        int v = (t >= off) ? ssum[t - off] : 0;
        __syncthreads();
        ssum[t] += v;
        __syncthreads();
    }
    int run = ssum[t] - s;
    for (int i = 0; i < CH; ++i) {
        int idx = base + i;
        if (idx < NN) {
            int d = deg[idx];
            rowptr[idx] = run;
            cursor[idx] = run;
            invdeg[idx] = 1.0f / fmaxf((float)d, 1.0f);
            run += d;
        }
    }
    if (t == 1023) rowptr[NN] = NE;
}
__global__ void fill_kernel(const int* __restrict__ src, const int* __restrict__ dst,
                            int* __restrict__ cursor, int* __restrict__ csr) {
    int e0 = (blockIdx.x * blockDim.x + threadIdx.x) * 4;
#pragma unroll
    for (int i = 0; i < 4; ++i) {
        int e = e0 + i;
        if (e < NE) {
            int d = __ldg(&dst[e]);
            int pos = atomicAdd(&cursor[d], 1);
            csr[pos] = __ldg(&src[e]);
        }
    }
}

// ---------------- weight prep: transpose+concat, fp16 hi/lo split ----------------
__global__ void prep_w(const float* __restrict__ Ws, const float* __restrict__ Wn,
                       __half* __restrict__ Bth, __half* __restrict__ Btl) {
    int i = blockIdx.x * blockDim.x + threadIdx.x;
    if (i >= DIM * 2 * DIM) return;
    int n = i >> 8;
    int k = i & 255;
    float w = (k < DIM) ? Ws[k * DIM + n] : Wn[(k - DIM) * DIM + n];
    __half hi = __float2half_rn(w);
    __half lo = __float2half_rn(w - __half2float(hi));
    Bth[i] = hi;
    Btl[i] = lo;
}

// ---------------- features -> fp16 ----------------
__global__ void feat_to_h16(const float* __restrict__ f, __half* __restrict__ o) {
    int i = blockIdx.x * blockDim.x + threadIdx.x;  // 8 elems each
    if (i >= NN * DIM / 8) return;
    const float4* p = (const float4*)f + (size_t)i * 2;
    float4 a = p[0], b = p[1];
    uint4 v;
    __half2 t0 = __floats2half2_rn(a.x, a.y);
    __half2 t1 = __floats2half2_rn(a.z, a.w);
    __half2 t2 = __floats2half2_rn(b.x, b.y);
    __half2 t3 = __floats2half2_rn(b.z, b.w);
    v.x = *(uint32_t*)&t0; v.y = *(uint32_t*)&t1;
    v.z = *(uint32_t*)&t2; v.w = *(uint32_t*)&t3;
    *((uint4*)o + i) = v;
}

// ---------------- CSR gather: acc16[n] = fp16(mean_{src in N(n)} h16[src]) ----------------
__global__ void __launch_bounds__(256)
gather16_kernel(const __half* __restrict__ h16, const int* __restrict__ rowptr,
                const int* __restrict__ csr, const float* __restrict__ invdeg,
                __half* __restrict__ acc16) {
    int node = blockIdx.x * 8 + (threadIdx.x >> 5);
    int lane = threadIdx.x & 31;
    if (node >= NN) return;
    int beg = __ldg(&rowptr[node]);
    int end = __ldg(&rowptr[node + 1]);
    float s0 = 0.f, s1 = 0.f, s2 = 0.f, s3 = 0.f;
    int i = beg;
    for (; i + 3 < end; i += 4) {
        int n0 = __ldg(&csr[i]), n1 = __ldg(&csr[i + 1]);
        int n2 = __ldg(&csr[i + 2]), n3 = __ldg(&csr[i + 3]);
        uint2 v0 = *(const uint2*)(h16 + (size_t)n0 * DIM + lane * 4);
        uint2 v1 = *(const uint2*)(h16 + (size_t)n1 * DIM + lane * 4);
        uint2 v2 = *(const uint2*)(h16 + (size_t)n2 * DIM + lane * 4);
        uint2 v3 = *(const uint2*)(h16 + (size_t)n3 * DIM + lane * 4);
#define ACC8(v)                                                     \
        {                                                           \
            float2 fa = __half22float2(*(__half2*)&(v).x);          \
            float2 fb = __half22float2(*(__half2*)&(v).y);          \
            s0 += fa.x; s1 += fa.y; s2 += fb.x; s3 += fb.y;         \
        }
        ACC8(v0) ACC8(v1) ACC8(v2) ACC8(v3)
    }
    for (; i < end; ++i) {
        int n0 = __ldg(&csr[i]);
        uint2 v0 = *(const uint2*)(h16 + (size_t)n0 * DIM + lane * 4);
        ACC8(v0)
    }
#undef ACC8
    float id = invdeg[node];
    __half2 o0 = __floats2half2_rn(s0 * id, s1 * id);
    __half2 o1 = __floats2half2_rn(s2 * id, s3 * id);
    uint2 o;
    o.x = *(uint32_t*)&o0; o.y = *(uint32_t*)&o1;
    *(uint2*)(acc16 + (size_t)node * DIM + lane * 4) = o;
}

// ---------------- fused SAGE GEMM: h16' = fp16(relu([h16|acc16] @ Bt^T + bias)) ----------------
// A fp16 1-term (cp.async staged), B fp16 hi/lo 2-term. 2-stage pipeline.
#define SA 0
#define SBH 16384
#define SBL 32768
#define STAGE 49152
#define SMEM_BYTES (2 * STAGE)

__global__ void __launch_bounds__(256, 1)
sage_gemm(const __half* __restrict__ h16, const __half* __restrict__ acc16,
          const __half* __restrict__ Bth, const __half* __restrict__ Btl,
          const float* __restrict__ bias, __half* __restrict__ out16) {
    extern __shared__ char sm[];
    const uint32_t sb = smem_u32(sm);
    const int t = threadIdx.x;
    const int lane = t & 31;
    const int wid = t >> 5;
    const int wm = wid & 3;
    const int wn = wid >> 2;
    const int row0 = blockIdx.x * 128;

    float cacc[2][8][4];
#pragma unroll
    for (int a = 0; a < 2; ++a)
#pragma unroll
        for (int b = 0; b < 8; ++b)
#pragma unroll
            for (int c = 0; c < 4; ++c) cacc[a][b][c] = 0.f;

    // stage(kc, s): async-copy A chunk + B chunks into stage s
    auto stage = [&](int kc, int s) {
        const __half* Asrc = (kc < 2) ? h16 : acc16;
        const int kbase = (kc & 1) * 64;
        const uint32_t sbase = sb + s * STAGE;
#pragma unroll
        for (int u = 0; u < 4; ++u) {
            int li = t + 256 * u;      // 0..1023
            int row = li >> 3, seg = li & 7;
            int r = row0 + row;
            const void* g = Asrc + (size_t)r * DIM + kbase + seg * 8;
            cpa16(sbase + SA + swz((uint32_t)(row * 128 + seg * 16)), g,
                  (r < NN) ? 16 : 0);
        }
#pragma unroll
        for (int u = 0; u < 4; ++u) {
            int li = t + 256 * u;
            int row = li >> 3, seg = li & 7;
            size_t gb = (size_t)row * 256 + kc * 64 + seg * 8;
            uint32_t off = swz((uint32_t)(row * 128 + seg * 16));
            cpa16(sbase + SBH + off, Bth + gb, 16);
            cpa16(sbase + SBL + off, Btl + gb, 16);
        }
        CP_COMMIT();
    };

    stage(0, 0);
    for (int kc = 0; kc < 4; ++kc) {
        const int cur = kc & 1;
        if (kc < 3) {
            stage(kc + 1, cur ^ 1);
            CP_WAIT(1);
        } else {
            CP_WAIT(0);
        }
        __syncthreads();

        const uint32_t sbase = sb + cur * STAGE;
#pragma unroll
        for (int ks = 0; ks < 4; ++ks) {
            uint32_t afr[2][4];
#pragma unroll
            for (int mt = 0; mt < 2; ++mt) {
                uint32_t row = wm * 32 + mt * 16 + (lane & 7) + ((lane >> 3) & 1) * 8;
                uint32_t cb = ks * 32 + ((lane >> 4) & 1) * 16;
                ldmx4(afr[mt], sbase + SA + swz(row * 128 + cb));
            }
#pragma unroll
            for (int np = 0; np < 4; ++np) {
                uint32_t nrow = wn * 64 + np * 16 + (lane & 7) + ((lane >> 4) & 1) * 8;
                uint32_t cb = ks * 32 + ((lane >> 3) & 1) * 16;
                uint32_t o = swz(nrow * 128 + cb);
                uint32_t bh[4], bl[4];
                ldmx4(bh, sbase + SBH + o);
                ldmx4(bl, sbase + SBL + o);
#pragma unroll
                for (int mt = 0; mt < 2; ++mt) {
                    mma16816(cacc[mt][2 * np], afr[mt], bh[0], bh[1]);
                    mma16816(cacc[mt][2 * np], afr[mt], bl[0], bl[1]);
                    mma16816(cacc[mt][2 * np + 1], afr[mt], bh[2], bh[3]);
                    mma16816(cacc[mt][2 * np + 1], afr[mt], bl[2], bl[3]);
                }
            }
        }
        __syncthreads();
    }

    // epilogue: +bias, relu, fp16 store
#pragma unroll
    for (int mt = 0; mt < 2; ++mt) {
        int r0 = row0 + wm * 32 + mt * 16 + (lane >> 2);
#pragma unroll
        for (int nt = 0; nt < 8; ++nt) {
            int c = wn * 64 + nt * 8 + (lane & 3) * 2;
            float b0 = __ldg(&bias[c]);
            float b1 = __ldg(&bias[c + 1]);
            float* cc = cacc[mt][nt];
            if (r0 < NN) {
                __half2 hv = __floats2half2_rn(fmaxf(cc[0] + b0, 0.f),
                                               fmaxf(cc[1] + b1, 0.f));
                *(__half2*)(out16 + (size_t)r0 * DIM + c) = hv;
            }
            int r1 = r0 + 8;
            if (r1 < NN) {
                __half2 hv = __floats2half2_rn(fmaxf(cc[2] + b0, 0.f),
                                               fmaxf(cc[3] + b1, 0.f));
                *(__half2*)(out16 + (size_t)r1 * DIM + c) = hv;
            }
        }
    }
}

// ---------------- mean graph pooling + classifier head ----------------
__global__ void __launch_bounds__(128)
pool_kernel(const __half* __restrict__ h16, const int* __restrict__ gids,
            const float* __restrict__ Wf, const float* __restrict__ bf,
            float* __restrict__ out) {
    __shared__ float pooled[DIM];
    int g = blockIdx.x;
    int t = threadIdx.x;

    int lo = 0, hi = NN;
    while (lo < hi) { int m = (lo + hi) >> 1; if (gids[m] < g) lo = m + 1; else hi = m; }
    int start = lo;
    lo = start; hi = NN;
    while (lo < hi) { int m = (lo + hi) >> 1; if (gids[m] < g + 1) lo = m + 1; else hi = m; }
    int end = lo;

    float s0 = 0.f, s1 = 0.f, s2 = 0.f, s3 = 0.f;
    int n = start;
    for (; n + 3 < end; n += 4) {
        s0 += __half2float(h16[(size_t)n * DIM + t]);
        s1 += __half2float(h16[(size_t)(n + 1) * DIM + t]);
        s2 += __half2float(h16[(size_t)(n + 2) * DIM + t]);
        s3 += __half2float(h16[(size_t)(n + 3) * DIM + t]);
    }
    for (; n < end; ++n) s0 += __half2float(h16[(size_t)n * DIM + t]);
    float cnt = fmaxf((float)(end - start), 1.0f);
    pooled[t] = ((s0 + s1) + (s2 + s3)) / cnt;
    __syncthreads();

    if (t < NCLS) {
        float o = bf[t];
#pragma unroll 8
        for (int k = 0; k < DIM; ++k) o = fmaf(pooled[k], Wf[k * NCLS + t], o);
        out[g * NCLS + t] = o;
    }
}

// ---------------- launch ----------------
extern "C" void kernel_launch(void* const* d_in, const int* in_sizes, int n_in,
                              void* d_out, int out_size) {
    const float* feat = (const float*)d_in[0];
    const int* esrc = (const int*)d_in[1];
    const int* edst = (const int*)d_in[2];
    const int* gids = (const int*)d_in[3];
    const float* Ws[3] = {(const float*)d_in[4], (const float*)d_in[7], (const float*)d_in[10]};
    const float* Wn[3] = {(const float*)d_in[5], (const float*)d_in[8], (const float*)d_in[11]};
    const float* bs[3] = {(const float*)d_in[6], (const float*)d_in[9], (const float*)d_in[12]};
    const float* Wf = (const float*)d_in[13];
    const float* bf = (const float*)d_in[14];
    float* out = (float*)d_out;

    __half *hA, *hB, *acc16, *Bth, *Btl;
    float* invdeg;
    int *deg, *rowptr, *cursor, *csr;
    cudaGetSymbolAddress((void**)&hA, g_hA);
    cudaGetSymbolAddress((void**)&hB, g_hB);
    cudaGetSymbolAddress((void**)&acc16, g_acc16);
    cudaGetSymbolAddress((void**)&invdeg, g_invdeg);
    cudaGetSymbolAddress((void**)&deg, g_deg);
    cudaGetSymbolAddress((void**)&rowptr, g_rowptr);
    cudaGetSymbolAddress((void**)&cursor, g_cursor);
    cudaGetSymbolAddress((void**)&csr, g_csr);
    cudaGetSymbolAddress((void**)&Bth, g_Bth);
    cudaGetSymbolAddress((void**)&Btl, g_Btl);

    cudaFuncSetAttribute(sage_gemm, cudaFuncAttributeMaxDynamicSharedMemorySize, SMEM_BYTES);

    // CSR build + invdeg
    zero_int<<<(NN + 255) / 256, 256>>>(deg, NN);
    hist_kernel<<<(NE / 4 + 255) / 256, 256>>>(edst, deg);
    scan_kernel<<<1, 1024>>>(deg, rowptr, cursor, invdeg);
    fill_kernel<<<(NE / 4 + 255) / 256, 256>>>(esrc, edst, cursor, csr);

    // weight prep + fp16 features
    const int wprep_blocks = (DIM * 2 * DIM + 255) / 256;
    for (int l = 0; l < 3; ++l)
        prep_w<<<wprep_blocks, 256>>>(Ws[l], Wn[l], Bth + l * DIM * 2 * DIM,
                                      Btl + l * DIM * 2 * DIM);
    feat_to_h16<<<(NN * DIM / 8 + 255) / 256, 256>>>(feat, hA);

    const int gemm_blocks = (NN + 127) / 128;
    const int gather_blocks = (NN + 7) / 8;

    __half* cur = hA;
    __half* nxt = hB;
    for (int l = 0; l < 3; ++l) {
        gather16_kernel<<<gather_blocks, 256>>>(cur, rowptr, csr, invdeg, acc16);
        sage_gemm<<<gemm_blocks, 256, SMEM_BYTES>>>(cur, acc16,
                                                    Bth + l * DIM * 2 * DIM,
                                                    Btl + l * DIM * 2 * DIM,
                                                    bs[l], nxt);
        __half* tmp = cur; cur = nxt; nxt = tmp;
    }

    pool_kernel<<<NG, 128>>>(cur, gids, Wf, bf, out);
}

// round 6
// speedup vs baseline: 2.4146x; 1.0058x over previous
#include <cuda_runtime.h>
#include <cuda_fp16.h>
#include <cstdint>
#include <math.h>

#define NN 50000
#define NE 800000
#define NG 128
#define DIM 128
#define NCLS 10

// ---------------- device scratch ----------------
__device__ __align__(16) __half g_hA[NN * DIM];
__device__ __align__(16) __half g_hB[NN * DIM];
__device__ __align__(16) __half g_acc16[NN * DIM];
__device__ float g_invdeg[NN];
__device__ int g_deg[NN];
__device__ int g_rowptr[NN + 1];
__device__ int g_cursor[NN];
__device__ int g_csr[NE];
// weights transposed+concat, fp16 hi/lo: [layer][n=128][k=256]
__device__ __align__(16) __half g_Bth[3 * DIM * 2 * DIM];
__device__ __align__(16) __half g_Btl[3 * DIM * 2 * DIM];

// ---------------- helpers ----------------
__device__ __forceinline__ uint32_t smem_u32(const void* p) {
    return (uint32_t)__cvta_generic_to_shared((void*)p);
}
__device__ __forceinline__ uint32_t swz(uint32_t x) { return x ^ (((x) >> 3) & 0x70); }

__device__ __forceinline__ void cpa16(uint32_t dst, const void* src, int sz) {
    asm volatile("cp.async.cg.shared.global [%0], [%1], 16, %2;"
                 :: "r"(dst), "l"(src), "r"(sz) : "memory");
}
#define CP_COMMIT() asm volatile("cp.async.commit_group;" ::: "memory")
#define CP_WAIT(n) asm volatile("cp.async.wait_group %0;" :: "n"(n) : "memory")

__device__ __forceinline__ void ldmx4(uint32_t* r, uint32_t a) {
    asm volatile("ldmatrix.sync.aligned.m8n8.x4.shared.b16 {%0,%1,%2,%3}, [%4];"
                 : "=r"(r[0]), "=r"(r[1]), "=r"(r[2]), "=r"(r[3]) : "r"(a));
}
__device__ __forceinline__ void mma16816(float* c, const uint32_t* a, uint32_t b0,
                                         uint32_t b1) {
    asm volatile(
        "mma.sync.aligned.m16n8k16.row.col.f32.f16.f16.f32 "
        "{%0,%1,%2,%3}, {%4,%5,%6,%7}, {%8,%9}, {%0,%1,%2,%3};"
        : "+f"(c[0]), "+f"(c[1]), "+f"(c[2]), "+f"(c[3])
        : "r"(a[0]), "r"(a[1]), "r"(a[2]), "r"(a[3]), "r"(b0), "r"(b1));
}

// ---------------- CSR build ----------------
__global__ void zero_int(int* p, int n) {
    int i = blockIdx.x * blockDim.x + threadIdx.x;
    if (i < n) p[i] = 0;
}
__global__ void hist_kernel(const int* __restrict__ dst, int* __restrict__ deg) {
    int e0 = (blockIdx.x * blockDim.x + threadIdx.x) * 8;
#pragma unroll
    for (int i = 0; i < 8; ++i)
        if (e0 + i < NE) atomicAdd(&deg[__ldg(&dst[e0 + i])], 1);
}
__global__ void __launch_bounds__(1024)
scan_kernel(const int* __restrict__ deg, int* __restrict__ rowptr,
            int* __restrict__ cursor, float* __restrict__ invdeg) {
    __shared__ int ssum[1024];
    const int t = threadIdx.x;
    const int CH = (NN + 1023) / 1024;
    const int base = t * CH;
    int s = 0;
    for (int i = 0; i < CH; ++i) {
        int idx = base + i;
        if (idx < NN) s += deg[idx];
    }
    ssum[t] = s;
    __syncthreads();
    for (int off = 1; off < 1024; off <<= 1) {
        int v = (t >= off) ? ssum[t - off] : 0;
        __syncthreads();
        ssum[t] += v;
        __syncthreads();
    }
    int run = ssum[t] - s;
    for (int i = 0; i < CH; ++i) {
        int idx = base + i;
        if (idx < NN) {
            int d = deg[idx];
            rowptr[idx] = run;
            cursor[idx] = run;
            invdeg[idx] = 1.0f / fmaxf((float)d, 1.0f);
            run += d;
        }
    }
    if (t == 1023) rowptr[NN] = NE;
}
__global__ void fill_kernel(const int* __restrict__ src, const int* __restrict__ dst,
                            int* __restrict__ cursor, int* __restrict__ csr) {
    int e0 = (blockIdx.x * blockDim.x + threadIdx.x) * 8;
#pragma unroll
    for (int i = 0; i < 8; ++i) {
        int e = e0 + i;
        if (e < NE) {
            int d = __ldg(&dst[e]);
            int pos = atomicAdd(&cursor[d], 1);
            csr[pos] = __ldg(&src[e]);
        }
    }
}

// ---------------- weight prep: transpose+concat, fp16 hi/lo split ----------------
__global__ void prep_w(const float* __restrict__ Ws, const float* __restrict__ Wn,
                       __half* __restrict__ Bth, __half* __restrict__ Btl) {
    int i = blockIdx.x * blockDim.x + threadIdx.x;
    if (i >= DIM * 2 * DIM) return;
    int n = i >> 8;
    int k = i & 255;
    float w = (k < DIM) ? Ws[k * DIM + n] : Wn[(k - DIM) * DIM + n];
    __half hi = __float2half_rn(w);
    __half lo = __float2half_rn(w - __half2float(hi));
    Bth[i] = hi;
    Btl[i] = lo;
}

// ---------------- features -> fp16 ----------------
__global__ void feat_to_h16(const float* __restrict__ f, __half* __restrict__ o) {
    int i = blockIdx.x * blockDim.x + threadIdx.x;  // 8 elems each
    if (i >= NN * DIM / 8) return;
    const float4* p = (const float4*)f + (size_t)i * 2;
    float4 a = p[0], b = p[1];
    uint4 v;
    __half2 t0 = __floats2half2_rn(a.x, a.y);
    __half2 t1 = __floats2half2_rn(a.z, a.w);
    __half2 t2 = __floats2half2_rn(b.x, b.y);
    __half2 t3 = __floats2half2_rn(b.z, b.w);
    v.x = *(uint32_t*)&t0; v.y = *(uint32_t*)&t1;
    v.z = *(uint32_t*)&t2; v.w = *(uint32_t*)&t3;
    *((uint4*)o + i) = v;
}

// ---------------- CSR gather: acc16[n] = fp16(mean_{src in N(n)} h16[src]) ----------------
__global__ void __launch_bounds__(256)
gather16_kernel(const __half* __restrict__ h16, const int* __restrict__ rowptr,
                const int* __restrict__ csr, const float* __restrict__ invdeg,
                __half* __restrict__ acc16) {
    int node = blockIdx.x * 8 + (threadIdx.x >> 5);
    int lane = threadIdx.x & 31;
    if (node >= NN) return;
    int beg = __ldg(&rowptr[node]);
    int end = __ldg(&rowptr[node + 1]);
    float s0 = 0.f, s1 = 0.f, s2 = 0.f, s3 = 0.f;
    int i = beg;
    for (; i + 3 < end; i += 4) {
        int n0 = __ldg(&csr[i]), n1 = __ldg(&csr[i + 1]);
        int n2 = __ldg(&csr[i + 2]), n3 = __ldg(&csr[i + 3]);
        uint2 v0 = *(const uint2*)(h16 + (size_t)n0 * DIM + lane * 4);
        uint2 v1 = *(const uint2*)(h16 + (size_t)n1 * DIM + lane * 4);
        uint2 v2 = *(const uint2*)(h16 + (size_t)n2 * DIM + lane * 4);
        uint2 v3 = *(const uint2*)(h16 + (size_t)n3 * DIM + lane * 4);
#define ACC8(v)                                                     \
        {                                                           \
            float2 fa = __half22float2(*(__half2*)&(v).x);          \
            float2 fb = __half22float2(*(__half2*)&(v).y);          \
            s0 += fa.x; s1 += fa.y; s2 += fb.x; s3 += fb.y;         \
        }
        ACC8(v0) ACC8(v1) ACC8(v2) ACC8(v3)
    }
    for (; i < end; ++i) {
        int n0 = __ldg(&csr[i]);
        uint2 v0 = *(const uint2*)(h16 + (size_t)n0 * DIM + lane * 4);
        ACC8(v0)
    }
#undef ACC8
    float id = invdeg[node];
    __half2 o0 = __floats2half2_rn(s0 * id, s1 * id);
    __half2 o1 = __floats2half2_rn(s2 * id, s3 * id);
    uint2 o;
    o.x = *(uint32_t*)&o0; o.y = *(uint32_t*)&o1;
    *(uint2*)(acc16 + (size_t)node * DIM + lane * 4) = o;
}

// ---------------- fused SAGE GEMM: h16' = fp16(relu([h16|acc16] @ Bt^T + bias)) ----------------
// A fp16 1-term, B fp16 hi/lo 2-term. Single 48KB stage, 2 CTAs/SM for
// cross-CTA latency hiding (R5 showed occupancy-1 leaves tensor pipe idle
// during cp.async wait + barriers).
#define SA 0
#define SBH 16384
#define SBL 32768
#define SMEM_BYTES 49152

__global__ void __launch_bounds__(256, 2)
sage_gemm(const __half* __restrict__ h16, const __half* __restrict__ acc16,
          const __half* __restrict__ Bth, const __half* __restrict__ Btl,
          const float* __restrict__ bias, __half* __restrict__ out16) {
    extern __shared__ char sm[];
    const uint32_t sb = smem_u32(sm);
    const int t = threadIdx.x;
    const int lane = t & 31;
    const int wid = t >> 5;
    const int wm = wid & 3;
    const int wn = wid >> 2;
    const int row0 = blockIdx.x * 128;

    float cacc[2][8][4];
#pragma unroll
    for (int a = 0; a < 2; ++a)
#pragma unroll
        for (int b = 0; b < 8; ++b)
#pragma unroll
            for (int c = 0; c < 4; ++c) cacc[a][b][c] = 0.f;

    for (int kc = 0; kc < 4; ++kc) {
        // ---- async stage A + B chunk kc ----
        {
            const __half* Asrc = (kc < 2) ? h16 : acc16;
            const int kbase = (kc & 1) * 64;
#pragma unroll
            for (int u = 0; u < 4; ++u) {
                int li = t + 256 * u;      // 0..1023
                int row = li >> 3, seg = li & 7;
                int r = row0 + row;
                const void* g = Asrc + (size_t)r * DIM + kbase + seg * 8;
                cpa16(sb + SA + swz((uint32_t)(row * 128 + seg * 16)), g,
                      (r < NN) ? 16 : 0);
            }
#pragma unroll
            for (int u = 0; u < 4; ++u) {
                int li = t + 256 * u;
                int row = li >> 3, seg = li & 7;
                size_t gb = (size_t)row * 256 + kc * 64 + seg * 8;
                uint32_t off = swz((uint32_t)(row * 128 + seg * 16));
                cpa16(sb + SBH + off, Bth + gb, 16);
                cpa16(sb + SBL + off, Btl + gb, 16);
            }
            CP_COMMIT();
        }
        CP_WAIT(0);
        __syncthreads();

#pragma unroll
        for (int ks = 0; ks < 4; ++ks) {
            uint32_t afr[2][4];
#pragma unroll
            for (int mt = 0; mt < 2; ++mt) {
                uint32_t row = wm * 32 + mt * 16 + (lane & 7) + ((lane >> 3) & 1) * 8;
                uint32_t cb = ks * 32 + ((lane >> 4) & 1) * 16;
                ldmx4(afr[mt], sb + SA + swz(row * 128 + cb));
            }
#pragma unroll
            for (int np = 0; np < 4; ++np) {
                uint32_t nrow = wn * 64 + np * 16 + (lane & 7) + ((lane >> 4) & 1) * 8;
                uint32_t cb = ks * 32 + ((lane >> 3) & 1) * 16;
                uint32_t o = swz(nrow * 128 + cb);
                uint32_t bh[4], bl[4];
                ldmx4(bh, sb + SBH + o);
                ldmx4(bl, sb + SBL + o);
#pragma unroll
                for (int mt = 0; mt < 2; ++mt) {
                    mma16816(cacc[mt][2 * np], afr[mt], bh[0], bh[1]);
                    mma16816(cacc[mt][2 * np], afr[mt], bl[0], bl[1]);
                    mma16816(cacc[mt][2 * np + 1], afr[mt], bh[2], bh[3]);
                    mma16816(cacc[mt][2 * np + 1], afr[mt], bl[2], bl[3]);
                }
            }
        }
        __syncthreads();
    }

    // epilogue: +bias, relu, fp16 store
#pragma unroll
    for (int mt = 0; mt < 2; ++mt) {
        int r0 = row0 + wm * 32 + mt * 16 + (lane >> 2);
#pragma unroll
        for (int nt = 0; nt < 8; ++nt) {
            int c = wn * 64 + nt * 8 + (lane & 3) * 2;
            float b0 = __ldg(&bias[c]);
            float b1 = __ldg(&bias[c + 1]);
            float* cc = cacc[mt][nt];
            if (r0 < NN) {
                __half2 hv = __floats2half2_rn(fmaxf(cc[0] + b0, 0.f),
                                               fmaxf(cc[1] + b1, 0.f));
                *(__half2*)(out16 + (size_t)r0 * DIM + c) = hv;
            }
            int r1 = r0 + 8;
            if (r1 < NN) {
                __half2 hv = __floats2half2_rn(fmaxf(cc[2] + b0, 0.f),
                                               fmaxf(cc[3] + b1, 0.f));
                *(__half2*)(out16 + (size_t)r1 * DIM + c) = hv;
            }
        }
    }
}

// ---------------- mean graph pooling + classifier head ----------------
__global__ void __launch_bounds__(128)
pool_kernel(const __half* __restrict__ h16, const int* __restrict__ gids,
            const float* __restrict__ Wf, const float* __restrict__ bf,
            float* __restrict__ out) {
    __shared__ float pooled[DIM];
    int g = blockIdx.x;
    int t = threadIdx.x;

    int lo = 0, hi = NN;
    while (lo < hi) { int m = (lo + hi) >> 1; if (gids[m] < g) lo = m + 1; else hi = m; }
    int start = lo;
    lo = start; hi = NN;
    while (lo < hi) { int m = (lo + hi) >> 1; if (gids[m] < g + 1) lo = m + 1; else hi = m; }
    int end = lo;

    float s0 = 0.f, s1 = 0.f, s2 = 0.f, s3 = 0.f;
    int n = start;
    for (; n + 3 < end; n += 4) {
        s0 += __half2float(h16[(size_t)n * DIM + t]);
        s1 += __half2float(h16[(size_t)(n + 1) * DIM + t]);
        s2 += __half2float(h16[(size_t)(n + 2) * DIM + t]);
        s3 += __half2float(h16[(size_t)(n + 3) * DIM + t]);
    }
    for (; n < end; ++n) s0 += __half2float(h16[(size_t)n * DIM + t]);
    float cnt = fmaxf((float)(end - start), 1.0f);
    pooled[t] = ((s0 + s1) + (s2 + s3)) / cnt;
    __syncthreads();

    if (t < NCLS) {
        float o = bf[t];
#pragma unroll 8
        for (int k = 0; k < DIM; ++k) o = fmaf(pooled[k], Wf[k * NCLS + t], o);
        out[g * NCLS + t] = o;
    }
}

// ---------------- launch ----------------
extern "C" void kernel_launch(void* const* d_in, const int* in_sizes, int n_in,
                              void* d_out, int out_size) {
    const float* feat = (const float*)d_in[0];
    const int* esrc = (const int*)d_in[1];
    const int* edst = (const int*)d_in[2];
    const int* gids = (const int*)d_in[3];
    const float* Ws[3] = {(const float*)d_in[4], (const float*)d_in[7], (const float*)d_in[10]};
    const float* Wn[3] = {(const float*)d_in[5], (const float*)d_in[8], (const float*)d_in[11]};
    const float* bs[3] = {(const float*)d_in[6], (const float*)d_in[9], (const float*)d_in[12]};
    const float* Wf = (const float*)d_in[13];
    const float* bf = (const float*)d_in[14];
    float* out = (float*)d_out;

    __half *hA, *hB, *acc16, *Bth, *Btl;
    float* invdeg;
    int *deg, *rowptr, *cursor, *csr;
    cudaGetSymbolAddress((void**)&hA, g_hA);
    cudaGetSymbolAddress((void**)&hB, g_hB);
    cudaGetSymbolAddress((void**)&acc16, g_acc16);
    cudaGetSymbolAddress((void**)&invdeg, g_invdeg);
    cudaGetSymbolAddress((void**)&deg, g_deg);
    cudaGetSymbolAddress((void**)&rowptr, g_rowptr);
    cudaGetSymbolAddress((void**)&cursor, g_cursor);
    cudaGetSymbolAddress((void**)&csr, g_csr);
    cudaGetSymbolAddress((void**)&Bth, g_Bth);
    cudaGetSymbolAddress((void**)&Btl, g_Btl);

    cudaFuncSetAttribute(sage_gemm, cudaFuncAttributeMaxDynamicSharedMemorySize, SMEM_BYTES);

    // CSR build + invdeg
    zero_int<<<(NN + 255) / 256, 256>>>(deg, NN);
    hist_kernel<<<(NE / 8 + 255) / 256, 256>>>(edst, deg);
    scan_kernel<<<1, 1024>>>(deg, rowptr, cursor, invdeg);
    fill_kernel<<<(NE / 8 + 255) / 256, 256>>>(esrc, edst, cursor, csr);

    // weight prep + fp16 features
    const int wprep_blocks = (DIM * 2 * DIM + 255) / 256;
    for (int l = 0; l < 3; ++l)
        prep_w<<<wprep_blocks, 256>>>(Ws[l], Wn[l], Bth + l * DIM * 2 * DIM,
                                      Btl + l * DIM * 2 * DIM);
    feat_to_h16<<<(NN * DIM / 8 + 255) / 256, 256>>>(feat, hA);

    const int gemm_blocks = (NN + 127) / 128;
    const int gather_blocks = (NN + 7) / 8;

    __half* cur = hA;
    __half* nxt = hB;
    for (int l = 0; l < 3; ++l) {
        gather16_kernel<<<gather_blocks, 256>>>(cur, rowptr, csr, invdeg, acc16);
        sage_gemm<<<gemm_blocks, 256, SMEM_BYTES>>>(cur, acc16,
                                                    Bth + l * DIM * 2 * DIM,
                                                    Btl + l * DIM * 2 * DIM,
                                                    bs[l], nxt);
        __half* tmp = cur; cur = nxt; nxt = tmp;
    }

    pool_kernel<<<NG, 128>>>(cur, gids, Wf, bf, out);
}

// round 7
// speedup vs baseline: 4.1597x; 1.7227x over previous
#include <cuda_runtime.h>
#include <cuda_fp16.h>
#include <cstdint>
#include <math.h>

#define NN 50000
#define NE 800000
#define NG 128
#define DIM 128
#define NCLS 10
#define SCAN_BLOCKS 196   // ceil(50000/256)

// ---------------- device scratch ----------------
__device__ __align__(16) __half g_hA[NN * DIM];
__device__ __align__(16) __half g_hB[NN * DIM];
__device__ __align__(16) __half g_acc16[NN * DIM];
__device__ float g_invdeg[NN];
__device__ int g_deg[NN];
__device__ int g_rowptr[NN + 1];
__device__ int g_cursor[NN];
__device__ int g_csr[NE];
__device__ int g_bsum[SCAN_BLOCKS];
__device__ int g_bpre[SCAN_BLOCKS];
// weights transposed+concat fp16 (1-term): [layer][n=128][k=256]
__device__ __align__(16) __half g_Bt[3 * DIM * 2 * DIM];

// ---------------- helpers ----------------
__device__ __forceinline__ uint32_t smem_u32(const void* p) {
    return (uint32_t)__cvta_generic_to_shared((void*)p);
}
__device__ __forceinline__ uint32_t swz(uint32_t x) { return x ^ (((x) >> 3) & 0x70); }

__device__ __forceinline__ void cpa16(uint32_t dst, const void* src, int sz) {
    asm volatile("cp.async.cg.shared.global [%0], [%1], 16, %2;"
                 :: "r"(dst), "l"(src), "r"(sz) : "memory");
}
#define CP_COMMIT() asm volatile("cp.async.commit_group;" ::: "memory")
#define CP_WAIT(n) asm volatile("cp.async.wait_group %0;" :: "n"(n) : "memory")

__device__ __forceinline__ void ldmx4(uint32_t* r, uint32_t a) {
    asm volatile("ldmatrix.sync.aligned.m8n8.x4.shared.b16 {%0,%1,%2,%3}, [%4];"
                 : "=r"(r[0]), "=r"(r[1]), "=r"(r[2]), "=r"(r[3]) : "r"(a));
}
__device__ __forceinline__ void mma16816(float* c, const uint32_t* a, uint32_t b0,
                                         uint32_t b1) {
    asm volatile(
        "mma.sync.aligned.m16n8k16.row.col.f32.f16.f16.f32 "
        "{%0,%1,%2,%3}, {%4,%5,%6,%7}, {%8,%9}, {%0,%1,%2,%3};"
        : "+f"(c[0]), "+f"(c[1]), "+f"(c[2]), "+f"(c[3])
        : "r"(a[0]), "r"(a[1]), "r"(a[2]), "r"(a[3]), "r"(b0), "r"(b1));
}

// ---------------- CSR build ----------------
__global__ void zero_int(int* p, int n) {
    int i = blockIdx.x * blockDim.x + threadIdx.x;
    if (i < n) p[i] = 0;
}
__global__ void hist_kernel(const int* __restrict__ dst, int* __restrict__ deg) {
    int e0 = (blockIdx.x * blockDim.x + threadIdx.x) * 8;
#pragma unroll
    for (int i = 0; i < 8; ++i)
        if (e0 + i < NE) atomicAdd(&deg[__ldg(&dst[e0 + i])], 1);
}
// multi-block scan, stage 1: per-block sums of 256 degrees
__global__ void __launch_bounds__(256)
scan1_kernel(const int* __restrict__ deg, int* __restrict__ bsum) {
    __shared__ int s[256];
    int t = threadIdx.x;
    int idx = blockIdx.x * 256 + t;
    s[t] = (idx < NN) ? deg[idx] : 0;
    __syncthreads();
#pragma unroll
    for (int off = 128; off > 0; off >>= 1) {
        if (t < off) s[t] += s[t + off];
        __syncthreads();
    }
    if (t == 0) bsum[blockIdx.x] = s[0];
}
// stage 2: single small block scans the block sums (196 entries)
__global__ void __launch_bounds__(256)
scan2_kernel(const int* __restrict__ bsum, int* __restrict__ bpre,
             int* __restrict__ rowptr) {
    __shared__ int s[256];
    int t = threadIdx.x;
    int v = (t < SCAN_BLOCKS) ? bsum[t] : 0;
    s[t] = v;
    __syncthreads();
#pragma unroll
    for (int off = 1; off < 256; off <<= 1) {
        int u = (t >= off) ? s[t - off] : 0;
        __syncthreads();
        s[t] += u;
        __syncthreads();
    }
    if (t < SCAN_BLOCKS) bpre[t] = s[t] - v;  // exclusive
    if (t == 0) rowptr[NN] = NE;
}
// stage 3: block-local scan + global offset -> rowptr/cursor/invdeg
__global__ void __launch_bounds__(256)
scan3_kernel(const int* __restrict__ deg, const int* __restrict__ bpre,
             int* __restrict__ rowptr, int* __restrict__ cursor,
             float* __restrict__ invdeg) {
    __shared__ int s[256];
    int t = threadIdx.x;
    int idx = blockIdx.x * 256 + t;
    int d = (idx < NN) ? deg[idx] : 0;
    s[t] = d;
    __syncthreads();
#pragma unroll
    for (int off = 1; off < 256; off <<= 1) {
        int u = (t >= off) ? s[t - off] : 0;
        __syncthreads();
        s[t] += u;
        __syncthreads();
    }
    if (idx < NN) {
        int pos = bpre[blockIdx.x] + s[t] - d;  // exclusive global prefix
        rowptr[idx] = pos;
        cursor[idx] = pos;
        invdeg[idx] = 1.0f / fmaxf((float)d, 1.0f);
    }
}
__global__ void fill_kernel(const int* __restrict__ src, const int* __restrict__ dst,
                            int* __restrict__ cursor, int* __restrict__ csr) {
    int e0 = (blockIdx.x * blockDim.x + threadIdx.x) * 8;
#pragma unroll
    for (int i = 0; i < 8; ++i) {
        int e = e0 + i;
        if (e < NE) {
            int d = __ldg(&dst[e]);
            int pos = atomicAdd(&cursor[d], 1);
            csr[pos] = __ldg(&src[e]);
        }
    }
}

// ---------------- weight prep: all 3 layers, transpose+concat, fp16 ----------------
__global__ void prep_w_all(const float* __restrict__ Ws0, const float* __restrict__ Wn0,
                           const float* __restrict__ Ws1, const float* __restrict__ Wn1,
                           const float* __restrict__ Ws2, const float* __restrict__ Wn2,
                           __half* __restrict__ Bt) {
    int i = blockIdx.x * blockDim.x + threadIdx.x;
    if (i >= 3 * DIM * 2 * DIM) return;
    int l = i / (DIM * 2 * DIM);
    int r = i - l * (DIM * 2 * DIM);
    int n = r >> 8;
    int k = r & 255;
    const float* Ws = (l == 0) ? Ws0 : (l == 1) ? Ws1 : Ws2;
    const float* Wn = (l == 0) ? Wn0 : (l == 1) ? Wn1 : Wn2;
    float w = (k < DIM) ? Ws[k * DIM + n] : Wn[(k - DIM) * DIM + n];
    Bt[i] = __float2half_rn(w);
}

// ---------------- features -> fp16 ----------------
__global__ void feat_to_h16(const float* __restrict__ f, __half* __restrict__ o) {
    int i = blockIdx.x * blockDim.x + threadIdx.x;  // 8 elems each
    if (i >= NN * DIM / 8) return;
    const float4* p = (const float4*)f + (size_t)i * 2;
    float4 a = p[0], b = p[1];
    uint4 v;
    __half2 t0 = __floats2half2_rn(a.x, a.y);
    __half2 t1 = __floats2half2_rn(a.z, a.w);
    __half2 t2 = __floats2half2_rn(b.x, b.y);
    __half2 t3 = __floats2half2_rn(b.z, b.w);
    v.x = *(uint32_t*)&t0; v.y = *(uint32_t*)&t1;
    v.z = *(uint32_t*)&t2; v.w = *(uint32_t*)&t3;
    *((uint4*)o + i) = v;
}

// ---------------- CSR gather: acc16[n] = fp16(mean_{src in N(n)} h16[src]) ----------------
__global__ void __launch_bounds__(256)
gather16_kernel(const __half* __restrict__ h16, const int* __restrict__ rowptr,
                const int* __restrict__ csr, const float* __restrict__ invdeg,
                __half* __restrict__ acc16) {
    int node = blockIdx.x * 8 + (threadIdx.x >> 5);
    int lane = threadIdx.x & 31;
    if (node >= NN) return;
    int beg = __ldg(&rowptr[node]);
    int end = __ldg(&rowptr[node + 1]);
    float s0 = 0.f, s1 = 0.f, s2 = 0.f, s3 = 0.f;
    int i = beg;
    for (; i + 3 < end; i += 4) {
        int n0 = __ldg(&csr[i]), n1 = __ldg(&csr[i + 1]);
        int n2 = __ldg(&csr[i + 2]), n3 = __ldg(&csr[i + 3]);
        uint2 v0 = *(const uint2*)(h16 + (size_t)n0 * DIM + lane * 4);
        uint2 v1 = *(const uint2*)(h16 + (size_t)n1 * DIM + lane * 4);
        uint2 v2 = *(const uint2*)(h16 + (size_t)n2 * DIM + lane * 4);
        uint2 v3 = *(const uint2*)(h16 + (size_t)n3 * DIM + lane * 4);
#define ACC8(v)                                                     \
        {                                                           \
            float2 fa = __half22float2(*(__half2*)&(v).x);          \
            float2 fb = __half22float2(*(__half2*)&(v).y);          \
            s0 += fa.x; s1 += fa.y; s2 += fb.x; s3 += fb.y;         \
        }
        ACC8(v0) ACC8(v1) ACC8(v2) ACC8(v3)
    }
    for (; i < end; ++i) {
        int n0 = __ldg(&csr[i]);
        uint2 v0 = *(const uint2*)(h16 + (size_t)n0 * DIM + lane * 4);
        ACC8(v0)
    }
#undef ACC8
    float id = invdeg[node];
    __half2 o0 = __floats2half2_rn(s0 * id, s1 * id);
    __half2 o1 = __floats2half2_rn(s2 * id, s3 * id);
    uint2 o;
    o.x = *(uint32_t*)&o0; o.y = *(uint32_t*)&o1;
    *(uint2*)(acc16 + (size_t)node * DIM + lane * 4) = o;
}

// ---------------- fused SAGE GEMM: h16' = fp16(relu([h16|acc16] @ Bt^T + bias)) ----------------
// 1-term fp16 A and B (HMMA-throughput bound: time ~ MMA count, so minimize it).
#define SA 0
#define SB 16384
#define SMEM_BYTES 32768

__global__ void __launch_bounds__(256, 2)
sage_gemm(const __half* __restrict__ h16, const __half* __restrict__ acc16,
          const __half* __restrict__ Bt, const float* __restrict__ bias,
          __half* __restrict__ out16) {
    extern __shared__ char sm[];
    const uint32_t sb = smem_u32(sm);
    const int t = threadIdx.x;
    const int lane = t & 31;
    const int wid = t >> 5;
    const int wm = wid & 3;
    const int wn = wid >> 2;
    const int row0 = blockIdx.x * 128;

    float cacc[2][8][4];
#pragma unroll
    for (int a = 0; a < 2; ++a)
#pragma unroll
        for (int b = 0; b < 8; ++b)
#pragma unroll
            for (int c = 0; c < 4; ++c) cacc[a][b][c] = 0.f;

    for (int kc = 0; kc < 4; ++kc) {
        // ---- async stage A + B chunk kc ----
        {
            const __half* Asrc = (kc < 2) ? h16 : acc16;
            const int kbase = (kc & 1) * 64;
#pragma unroll
            for (int u = 0; u < 4; ++u) {
                int li = t + 256 * u;      // 0..1023
                int row = li >> 3, seg = li & 7;
                int r = row0 + row;
                const void* g = Asrc + (size_t)r * DIM + kbase + seg * 8;
                cpa16(sb + SA + swz((uint32_t)(row * 128 + seg * 16)), g,
                      (r < NN) ? 16 : 0);
            }
#pragma unroll
            for (int u = 0; u < 4; ++u) {
                int li = t + 256 * u;
                int row = li >> 3, seg = li & 7;
                size_t gb = (size_t)row * 256 + kc * 64 + seg * 8;
                cpa16(sb + SB + swz((uint32_t)(row * 128 + seg * 16)), Bt + gb, 16);
            }
            CP_COMMIT();
        }
        CP_WAIT(0);
        __syncthreads();

#pragma unroll
        for (int ks = 0; ks < 4; ++ks) {
            uint32_t afr[2][4];
#pragma unroll
            for (int mt = 0; mt < 2; ++mt) {
                uint32_t row = wm * 32 + mt * 16 + (lane & 7) + ((lane >> 3) & 1) * 8;
                uint32_t cb = ks * 32 + ((lane >> 4) & 1) * 16;
                ldmx4(afr[mt], sb + SA + swz(row * 128 + cb));
            }
#pragma unroll
            for (int np = 0; np < 4; ++np) {
                uint32_t nrow = wn * 64 + np * 16 + (lane & 7) + ((lane >> 4) & 1) * 8;
                uint32_t cb = ks * 32 + ((lane >> 3) & 1) * 16;
                uint32_t bh[4];
                ldmx4(bh, sb + SB + swz(nrow * 128 + cb));
#pragma unroll
                for (int mt = 0; mt < 2; ++mt) {
                    mma16816(cacc[mt][2 * np], afr[mt], bh[0], bh[1]);
                    mma16816(cacc[mt][2 * np + 1], afr[mt], bh[2], bh[3]);
                }
            }
        }
        __syncthreads();
    }

    // epilogue: +bias, relu, fp16 store
#pragma unroll
    for (int mt = 0; mt < 2; ++mt) {
        int r0 = row0 + wm * 32 + mt * 16 + (lane >> 2);
#pragma unroll
        for (int nt = 0; nt < 8; ++nt) {
            int c = wn * 64 + nt * 8 + (lane & 3) * 2;
            float b0 = __ldg(&bias[c]);
            float b1 = __ldg(&bias[c + 1]);
            float* cc = cacc[mt][nt];
            if (r0 < NN) {
                __half2 hv = __floats2half2_rn(fmaxf(cc[0] + b0, 0.f),
                                               fmaxf(cc[1] + b1, 0.f));
                *(__half2*)(out16 + (size_t)r0 * DIM + c) = hv;
            }
            int r1 = r0 + 8;
            if (r1 < NN) {
                __half2 hv = __floats2half2_rn(fmaxf(cc[2] + b0, 0.f),
                                               fmaxf(cc[3] + b1, 0.f));
                *(__half2*)(out16 + (size_t)r1 * DIM + c) = hv;
            }
        }
    }
}

// ---------------- mean graph pooling + classifier head ----------------
__global__ void __launch_bounds__(128)
pool_kernel(const __half* __restrict__ h16, const int* __restrict__ gids,
            const float* __restrict__ Wf, const float* __restrict__ bf,
            float* __restrict__ out) {
    __shared__ float pooled[DIM];
    int g = blockIdx.x;
    int t = threadIdx.x;

    int lo = 0, hi = NN;
    while (lo < hi) { int m = (lo + hi) >> 1; if (gids[m] < g) lo = m + 1; else hi = m; }
    int start = lo;
    lo = start; hi = NN;
    while (lo < hi) { int m = (lo + hi) >> 1; if (gids[m] < g + 1) lo = m + 1; else hi = m; }
    int end = lo;

    float s0 = 0.f, s1 = 0.f, s2 = 0.f, s3 = 0.f;
    int n = start;
    for (; n + 3 < end; n += 4) {
        s0 += __half2float(h16[(size_t)n * DIM + t]);
        s1 += __half2float(h16[(size_t)(n + 1) * DIM + t]);
        s2 += __half2float(h16[(size_t)(n + 2) * DIM + t]);
        s3 += __half2float(h16[(size_t)(n + 3) * DIM + t]);
    }
    for (; n < end; ++n) s0 += __half2float(h16[(size_t)n * DIM + t]);
    float cnt = fmaxf((float)(end - start), 1.0f);
    pooled[t] = ((s0 + s1) + (s2 + s3)) / cnt;
    __syncthreads();

    if (t < NCLS) {
        float o = bf[t];
#pragma unroll 8
        for (int k = 0; k < DIM; ++k) o = fmaf(pooled[k], Wf[k * NCLS + t], o);
        out[g * NCLS + t] = o;
    }
}

// ---------------- launch ----------------
extern "C" void kernel_launch(void* const* d_in, const int* in_sizes, int n_in,
                              void* d_out, int out_size) {
    const float* feat = (const float*)d_in[0];
    const int* esrc = (const int*)d_in[1];
    const int* edst = (const int*)d_in[2];
    const int* gids = (const int*)d_in[3];
    const float* Ws[3] = {(const float*)d_in[4], (const float*)d_in[7], (const float*)d_in[10]};
    const float* Wn[3] = {(const float*)d_in[5], (const float*)d_in[8], (const float*)d_in[11]};
    const float* bs[3] = {(const float*)d_in[6], (const float*)d_in[9], (const float*)d_in[12]};
    const float* Wf = (const float*)d_in[13];
    const float* bf = (const float*)d_in[14];
    float* out = (float*)d_out;

    __half *hA, *hB, *acc16, *Bt;
    float* invdeg;
    int *deg, *rowptr, *cursor, *csr, *bsum, *bpre;
    cudaGetSymbolAddress((void**)&hA, g_hA);
    cudaGetSymbolAddress((void**)&hB, g_hB);
    cudaGetSymbolAddress((void**)&acc16, g_acc16);
    cudaGetSymbolAddress((void**)&invdeg, g_invdeg);
    cudaGetSymbolAddress((void**)&deg, g_deg);
    cudaGetSymbolAddress((void**)&rowptr, g_rowptr);
    cudaGetSymbolAddress((void**)&cursor, g_cursor);
    cudaGetSymbolAddress((void**)&csr, g_csr);
    cudaGetSymbolAddress((void**)&bsum, g_bsum);
    cudaGetSymbolAddress((void**)&bpre, g_bpre);
    cudaGetSymbolAddress((void**)&Bt, g_Bt);

    cudaFuncSetAttribute(sage_gemm, cudaFuncAttributeMaxDynamicSharedMemorySize, SMEM_BYTES);

    // CSR build + invdeg (multi-block scan)
    zero_int<<<(NN + 255) / 256, 256>>>(deg, NN);
    hist_kernel<<<(NE / 8 + 255) / 256, 256>>>(edst, deg);
    scan1_kernel<<<SCAN_BLOCKS, 256>>>(deg, bsum);
    scan2_kernel<<<1, 256>>>(bsum, bpre, rowptr);
    scan3_kernel<<<SCAN_BLOCKS, 256>>>(deg, bpre, rowptr, cursor, invdeg);
    fill_kernel<<<(NE / 8 + 255) / 256, 256>>>(esrc, edst, cursor, csr);

    // weight prep (all layers) + fp16 features
    prep_w_all<<<(3 * DIM * 2 * DIM + 255) / 256, 256>>>(
        Ws[0], Wn[0], Ws[1], Wn[1], Ws[2], Wn[2], Bt);
    feat_to_h16<<<(NN * DIM / 8 + 255) / 256, 256>>>(feat, hA);

    const int gemm_blocks = (NN + 127) / 128;
    const int gather_blocks = (NN + 7) / 8;

    __half* cur = hA;
    __half* nxt = hB;
    for (int l = 0; l < 3; ++l) {
        gather16_kernel<<<gather_blocks, 256>>>(cur, rowptr, csr, invdeg, acc16);
        sage_gemm<<<gemm_blocks, 256, SMEM_BYTES>>>(cur, acc16,
                                                    Bt + l * DIM * 2 * DIM,
                                                    bs[l], nxt);
        __half* tmp = cur; cur = nxt; nxt = tmp;
    }

    pool_kernel<<<NG, 128>>>(cur, gids, Wf, bf, out);
}

// round 8
// speedup vs baseline: 4.4195x; 1.0625x over previous
#include <cuda_runtime.h>
#include <cuda_fp16.h>
#include <cstdint>
#include <math.h>

#define NN 50000
#define NE 800000
#define NG 128
#define DIM 128
#define NCLS 10
#define SCAN_BLOCKS 196   // ceil(50000/256)

// ---------------- device scratch ----------------
__device__ __align__(16) __half g_hA[NN * DIM];
__device__ __align__(16) __half g_hB[NN * DIM];
__device__ __align__(16) __half g_acc16[NN * DIM];
__device__ float g_invdeg[NN];
__device__ int g_deg[NN];
__device__ int g_rowptr[NN + 1];
__device__ int g_cursor[NN];
__device__ int g_csr[NE];
__device__ int g_bsum[SCAN_BLOCKS];
__device__ int g_bpre[SCAN_BLOCKS];
// weights transposed+concat fp16 (1-term): [layer][n=128][k=256]
__device__ __align__(16) __half g_Bt[3 * DIM * 2 * DIM];

// ---------------- helpers ----------------
__device__ __forceinline__ uint32_t smem_u32(const void* p) {
    return (uint32_t)__cvta_generic_to_shared((void*)p);
}
__device__ __forceinline__ uint32_t swz(uint32_t x) { return x ^ (((x) >> 3) & 0x70); }

__device__ __forceinline__ void cpa16(uint32_t dst, const void* src, int sz) {
    asm volatile("cp.async.cg.shared.global [%0], [%1], 16, %2;"
                 :: "r"(dst), "l"(src), "r"(sz) : "memory");
}
#define CP_COMMIT() asm volatile("cp.async.commit_group;" ::: "memory")
#define CP_WAIT(n) asm volatile("cp.async.wait_group %0;" :: "n"(n) : "memory")

__device__ __forceinline__ void ldmx4(uint32_t* r, uint32_t a) {
    asm volatile("ldmatrix.sync.aligned.m8n8.x4.shared.b16 {%0,%1,%2,%3}, [%4];"
                 : "=r"(r[0]), "=r"(r[1]), "=r"(r[2]), "=r"(r[3]) : "r"(a));
}
__device__ __forceinline__ void mma16816(float* c, const uint32_t* a, uint32_t b0,
                                         uint32_t b1) {
    asm volatile(
        "mma.sync.aligned.m16n8k16.row.col.f32.f16.f16.f32 "
        "{%0,%1,%2,%3}, {%4,%5,%6,%7}, {%8,%9}, {%0,%1,%2,%3};"
        : "+f"(c[0]), "+f"(c[1]), "+f"(c[2]), "+f"(c[3])
        : "r"(a[0]), "r"(a[1]), "r"(a[2]), "r"(a[3]), "r"(b0), "r"(b1));
}

// ---------------- CSR build ----------------
__global__ void zero_int(int* p, int n) {
    int i = blockIdx.x * blockDim.x + threadIdx.x;
    if (i < n) p[i] = 0;
}
// ILP-16 histogram with int4 vector loads (NE = 50000*16 exactly)
__global__ void hist_kernel(const int4* __restrict__ dst4, int* __restrict__ deg) {
    int tid = blockIdx.x * blockDim.x + threadIdx.x;
    if (tid >= NE / 16) return;
    int4 d[4];
#pragma unroll
    for (int j = 0; j < 4; ++j) d[j] = __ldg(&dst4[tid * 4 + j]);
    const int* dd = (const int*)d;
#pragma unroll
    for (int i = 0; i < 16; ++i) atomicAdd(&deg[dd[i]], 1);
}
// multi-block scan, stage 1: per-block sums of 256 degrees
__global__ void __launch_bounds__(256)
scan1_kernel(const int* __restrict__ deg, int* __restrict__ bsum) {
    __shared__ int s[256];
    int t = threadIdx.x;
    int idx = blockIdx.x * 256 + t;
    s[t] = (idx < NN) ? deg[idx] : 0;
    __syncthreads();
#pragma unroll
    for (int off = 128; off > 0; off >>= 1) {
        if (t < off) s[t] += s[t + off];
        __syncthreads();
    }
    if (t == 0) bsum[blockIdx.x] = s[0];
}
// stage 2: single small block scans the block sums (196 entries)
__global__ void __launch_bounds__(256)
scan2_kernel(const int* __restrict__ bsum, int* __restrict__ bpre,
             int* __restrict__ rowptr) {
    __shared__ int s[256];
    int t = threadIdx.x;
    int v = (t < SCAN_BLOCKS) ? bsum[t] : 0;
    s[t] = v;
    __syncthreads();
#pragma unroll
    for (int off = 1; off < 256; off <<= 1) {
        int u = (t >= off) ? s[t - off] : 0;
        __syncthreads();
        s[t] += u;
        __syncthreads();
    }
    if (t < SCAN_BLOCKS) bpre[t] = s[t] - v;  // exclusive
    if (t == 0) rowptr[NN] = NE;
}
// stage 3: block-local scan + global offset -> rowptr/cursor/invdeg
__global__ void __launch_bounds__(256)
scan3_kernel(const int* __restrict__ deg, const int* __restrict__ bpre,
             int* __restrict__ rowptr, int* __restrict__ cursor,
             float* __restrict__ invdeg) {
    __shared__ int s[256];
    int t = threadIdx.x;
    int idx = blockIdx.x * 256 + t;
    int d = (idx < NN) ? deg[idx] : 0;
    s[t] = d;
    __syncthreads();
#pragma unroll
    for (int off = 1; off < 256; off <<= 1) {
        int u = (t >= off) ? s[t - off] : 0;
        __syncthreads();
        s[t] += u;
        __syncthreads();
    }
    if (idx < NN) {
        int pos = bpre[blockIdx.x] + s[t] - d;  // exclusive global prefix
        rowptr[idx] = pos;
        cursor[idx] = pos;
        invdeg[idx] = 1.0f / fmaxf((float)d, 1.0f);
    }
}
// ILP-16 CSR fill with int4 vector loads
__global__ void fill_kernel(const int4* __restrict__ src4, const int4* __restrict__ dst4,
                            int* __restrict__ cursor, int* __restrict__ csr) {
    int tid = blockIdx.x * blockDim.x + threadIdx.x;
    if (tid >= NE / 16) return;
    int4 d[4], sr[4];
#pragma unroll
    for (int j = 0; j < 4; ++j) {
        d[j] = __ldg(&dst4[tid * 4 + j]);
        sr[j] = __ldg(&src4[tid * 4 + j]);
    }
    const int* dd = (const int*)d;
    const int* ss = (const int*)sr;
    int pos[16];
#pragma unroll
    for (int i = 0; i < 16; ++i) pos[i] = atomicAdd(&cursor[dd[i]], 1);
#pragma unroll
    for (int i = 0; i < 16; ++i) csr[pos[i]] = ss[i];
}

// ---------------- weight prep: all 3 layers, transpose+concat, fp16 ----------------
__global__ void prep_w_all(const float* __restrict__ Ws0, const float* __restrict__ Wn0,
                           const float* __restrict__ Ws1, const float* __restrict__ Wn1,
                           const float* __restrict__ Ws2, const float* __restrict__ Wn2,
                           __half* __restrict__ Bt) {
    int i = blockIdx.x * blockDim.x + threadIdx.x;
    if (i >= 3 * DIM * 2 * DIM) return;
    int l = i / (DIM * 2 * DIM);
    int r = i - l * (DIM * 2 * DIM);
    int n = r >> 8;
    int k = r & 255;
    const float* Ws = (l == 0) ? Ws0 : (l == 1) ? Ws1 : Ws2;
    const float* Wn = (l == 0) ? Wn0 : (l == 1) ? Wn1 : Wn2;
    float w = (k < DIM) ? Ws[k * DIM + n] : Wn[(k - DIM) * DIM + n];
    Bt[i] = __float2half_rn(w);
}

// ---------------- features -> fp16 ----------------
__global__ void feat_to_h16(const float* __restrict__ f, __half* __restrict__ o) {
    int i = blockIdx.x * blockDim.x + threadIdx.x;  // 8 elems each
    if (i >= NN * DIM / 8) return;
    const float4* p = (const float4*)f + (size_t)i * 2;
    float4 a = p[0], b = p[1];
    uint4 v;
    __half2 t0 = __floats2half2_rn(a.x, a.y);
    __half2 t1 = __floats2half2_rn(a.z, a.w);
    __half2 t2 = __floats2half2_rn(b.x, b.y);
    __half2 t3 = __floats2half2_rn(b.z, b.w);
    v.x = *(uint32_t*)&t0; v.y = *(uint32_t*)&t1;
    v.z = *(uint32_t*)&t2; v.w = *(uint32_t*)&t3;
    *((uint4*)o + i) = v;
}

// ---------------- CSR gather: acc16[n] = fp16(mean_{src in N(n)} h16[src]) ----------------
__global__ void __launch_bounds__(256)
gather16_kernel(const __half* __restrict__ h16, const int* __restrict__ rowptr,
                const int* __restrict__ csr, const float* __restrict__ invdeg,
                __half* __restrict__ acc16) {
    int node = blockIdx.x * 8 + (threadIdx.x >> 5);
    int lane = threadIdx.x & 31;
    if (node >= NN) return;
    int beg = __ldg(&rowptr[node]);
    int end = __ldg(&rowptr[node + 1]);
    float s0 = 0.f, s1 = 0.f, s2 = 0.f, s3 = 0.f;
    int i = beg;
    for (; i + 3 < end; i += 4) {
        int n0 = __ldg(&csr[i]), n1 = __ldg(&csr[i + 1]);
        int n2 = __ldg(&csr[i + 2]), n3 = __ldg(&csr[i + 3]);
        uint2 v0 = *(const uint2*)(h16 + (size_t)n0 * DIM + lane * 4);
        uint2 v1 = *(const uint2*)(h16 + (size_t)n1 * DIM + lane * 4);
        uint2 v2 = *(const uint2*)(h16 + (size_t)n2 * DIM + lane * 4);
        uint2 v3 = *(const uint2*)(h16 + (size_t)n3 * DIM + lane * 4);
#define ACC8(v)                                                     \
        {                                                           \
            float2 fa = __half22float2(*(__half2*)&(v).x);          \
            float2 fb = __half22float2(*(__half2*)&(v).y);          \
            s0 += fa.x; s1 += fa.y; s2 += fb.x; s3 += fb.y;         \
        }
        ACC8(v0) ACC8(v1) ACC8(v2) ACC8(v3)
    }
    for (; i < end; ++i) {
        int n0 = __ldg(&csr[i]);
        uint2 v0 = *(const uint2*)(h16 + (size_t)n0 * DIM + lane * 4);
        ACC8(v0)
    }
#undef ACC8
    float id = invdeg[node];
    __half2 o0 = __floats2half2_rn(s0 * id, s1 * id);
    __half2 o1 = __floats2half2_rn(s2 * id, s3 * id);
    uint2 o;
    o.x = *(uint32_t*)&o0; o.y = *(uint32_t*)&o1;
    *(uint2*)(acc16 + (size_t)node * DIM + lane * 4) = o;
}

// ---------------- fused SAGE GEMM: h16' = fp16(relu([h16|acc16] @ Bt^T + bias)) ----------------
#define SA 0
#define SB 16384
#define SMEM_BYTES 32768

__global__ void __launch_bounds__(256, 2)
sage_gemm(const __half* __restrict__ h16, const __half* __restrict__ acc16,
          const __half* __restrict__ Bt, const float* __restrict__ bias,
          __half* __restrict__ out16) {
    extern __shared__ char sm[];
    const uint32_t sb = smem_u32(sm);
    const int t = threadIdx.x;
    const int lane = t & 31;
    const int wid = t >> 5;
    const int wm = wid & 3;
    const int wn = wid >> 2;
    const int row0 = blockIdx.x * 128;

    float cacc[2][8][4];
#pragma unroll
    for (int a = 0; a < 2; ++a)
#pragma unroll
        for (int b = 0; b < 8; ++b)
#pragma unroll
            for (int c = 0; c < 4; ++c) cacc[a][b][c] = 0.f;

    for (int kc = 0; kc < 4; ++kc) {
        // ---- async stage A + B chunk kc ----
        {
            const __half* Asrc = (kc < 2) ? h16 : acc16;
            const int kbase = (kc & 1) * 64;
#pragma unroll
            for (int u = 0; u < 4; ++u) {
                int li = t + 256 * u;      // 0..1023
                int row = li >> 3, seg = li & 7;
                int r = row0 + row;
                const void* g = Asrc + (size_t)r * DIM + kbase + seg * 8;
                cpa16(sb + SA + swz((uint32_t)(row * 128 + seg * 16)), g,
                      (r < NN) ? 16 : 0);
            }
#pragma unroll
            for (int u = 0; u < 4; ++u) {
                int li = t + 256 * u;
                int row = li >> 3, seg = li & 7;
                size_t gb = (size_t)row * 256 + kc * 64 + seg * 8;
                cpa16(sb + SB + swz((uint32_t)(row * 128 + seg * 16)), Bt + gb, 16);
            }
            CP_COMMIT();
        }
        CP_WAIT(0);
        __syncthreads();

#pragma unroll
        for (int ks = 0; ks < 4; ++ks) {
            uint32_t afr[2][4];
#pragma unroll
            for (int mt = 0; mt < 2; ++mt) {
                uint32_t row = wm * 32 + mt * 16 + (lane & 7) + ((lane >> 3) & 1) * 8;
                uint32_t cb = ks * 32 + ((lane >> 4) & 1) * 16;
                ldmx4(afr[mt], sb + SA + swz(row * 128 + cb));
            }
#pragma unroll
            for (int np = 0; np < 4; ++np) {
                uint32_t nrow = wn * 64 + np * 16 + (lane & 7) + ((lane >> 4) & 1) * 8;
                uint32_t cb = ks * 32 + ((lane >> 3) & 1) * 16;
                uint32_t bh[4];
                ldmx4(bh, sb + SB + swz(nrow * 128 + cb));
#pragma unroll
                for (int mt = 0; mt < 2; ++mt) {
                    mma16816(cacc[mt][2 * np], afr[mt], bh[0], bh[1]);
                    mma16816(cacc[mt][2 * np + 1], afr[mt], bh[2], bh[3]);
                }
            }
        }
        __syncthreads();
    }

    // epilogue: +bias, relu, fp16 store
#pragma unroll
    for (int mt = 0; mt < 2; ++mt) {
        int r0 = row0 + wm * 32 + mt * 16 + (lane >> 2);
#pragma unroll
        for (int nt = 0; nt < 8; ++nt) {
            int c = wn * 64 + nt * 8 + (lane & 3) * 2;
            float b0 = __ldg(&bias[c]);
            float b1 = __ldg(&bias[c + 1]);
            float* cc = cacc[mt][nt];
            if (r0 < NN) {
                __half2 hv = __floats2half2_rn(fmaxf(cc[0] + b0, 0.f),
                                               fmaxf(cc[1] + b1, 0.f));
                *(__half2*)(out16 + (size_t)r0 * DIM + c) = hv;
            }
            int r1 = r0 + 8;
            if (r1 < NN) {
                __half2 hv = __floats2half2_rn(fmaxf(cc[2] + b0, 0.f),
                                               fmaxf(cc[3] + b1, 0.f));
                *(__half2*)(out16 + (size_t)r1 * DIM + c) = hv;
            }
        }
    }
}

// ---------------- mean graph pooling + classifier head ----------------
// 512 threads: 4 node-lanes x 128 cols, smem reduce across lanes.
__global__ void __launch_bounds__(512)
pool_kernel(const __half* __restrict__ h16, const int* __restrict__ gids,
            const float* __restrict__ Wf, const float* __restrict__ bf,
            float* __restrict__ out) {
    __shared__ float part[4][DIM];
    __shared__ float pooled[DIM];
    int g = blockIdx.x;
    int t = threadIdx.x;
    int nl = t >> 7;        // node lane 0..3
    int col = t & 127;

    int lo = 0, hi = NN;
    while (lo < hi) { int m = (lo + hi) >> 1; if (__ldg(&gids[m]) < g) lo = m + 1; else hi = m; }
    int start = lo;
    lo = start; hi = NN;
    while (lo < hi) { int m = (lo + hi) >> 1; if (__ldg(&gids[m]) < g + 1) lo = m + 1; else hi = m; }
    int end = lo;

    float s = 0.f;
    for (int n = start + nl; n < end; n += 4)
        s += __half2float(h16[(size_t)n * DIM + col]);
    part[nl][col] = s;
    __syncthreads();

    if (nl == 0) {
        float cnt = fmaxf((float)(end - start), 1.0f);
        pooled[col] = (part[0][col] + part[1][col] + part[2][col] + part[3][col]) / cnt;
    }
    __syncthreads();

    if (t < NCLS) {
        float o = bf[t];
#pragma unroll 8
        for (int k = 0; k < DIM; ++k) o = fmaf(pooled[k], Wf[k * NCLS + t], o);
        out[g * NCLS + t] = o;
    }
}

// ---------------- launch ----------------
extern "C" void kernel_launch(void* const* d_in, const int* in_sizes, int n_in,
                              void* d_out, int out_size) {
    const float* feat = (const float*)d_in[0];
    const int* esrc = (const int*)d_in[1];
    const int* edst = (const int*)d_in[2];
    const int* gids = (const int*)d_in[3];
    const float* Ws[3] = {(const float*)d_in[4], (const float*)d_in[7], (const float*)d_in[10]};
    const float* Wn[3] = {(const float*)d_in[5], (const float*)d_in[8], (const float*)d_in[11]};
    const float* bs[3] = {(const float*)d_in[6], (const float*)d_in[9], (const float*)d_in[12]};
    const float* Wf = (const float*)d_in[13];
    const float* bf = (const float*)d_in[14];
    float* out = (float*)d_out;

    __half *hA, *hB, *acc16, *Bt;
    float* invdeg;
    int *deg, *rowptr, *cursor, *csr, *bsum, *bpre;
    cudaGetSymbolAddress((void**)&hA, g_hA);
    cudaGetSymbolAddress((void**)&hB, g_hB);
    cudaGetSymbolAddress((void**)&acc16, g_acc16);
    cudaGetSymbolAddress((void**)&invdeg, g_invdeg);
    cudaGetSymbolAddress((void**)&deg, g_deg);
    cudaGetSymbolAddress((void**)&rowptr, g_rowptr);
    cudaGetSymbolAddress((void**)&cursor, g_cursor);
    cudaGetSymbolAddress((void**)&csr, g_csr);
    cudaGetSymbolAddress((void**)&bsum, g_bsum);
    cudaGetSymbolAddress((void**)&bpre, g_bpre);
    cudaGetSymbolAddress((void**)&Bt, g_Bt);

    cudaFuncSetAttribute(sage_gemm, cudaFuncAttributeMaxDynamicSharedMemorySize, SMEM_BYTES);

    // CSR build + invdeg (multi-block scan)
    zero_int<<<(NN + 255) / 256, 256>>>(deg, NN);
    hist_kernel<<<(NE / 16 + 255) / 256, 256>>>((const int4*)edst, deg);
    scan1_kernel<<<SCAN_BLOCKS, 256>>>(deg, bsum);
    scan2_kernel<<<1, 256>>>(bsum, bpre, rowptr);
    scan3_kernel<<<SCAN_BLOCKS, 256>>>(deg, bpre, rowptr, cursor, invdeg);
    fill_kernel<<<(NE / 16 + 255) / 256, 256>>>((const int4*)esrc, (const int4*)edst,
                                                cursor, csr);

    // weight prep (all layers) + fp16 features
    prep_w_all<<<(3 * DIM * 2 * DIM + 255) / 256, 256>>>(
        Ws[0], Wn[0], Ws[1], Wn[1], Ws[2], Wn[2], Bt);
    feat_to_h16<<<(NN * DIM / 8 + 255) / 256, 256>>>(feat, hA);

    const int gemm_blocks = (NN + 127) / 128;
    const int gather_blocks = (NN + 7) / 8;

    __half* cur = hA;
    __half* nxt = hB;
    for (int l = 0; l < 3; ++l) {
        gather16_kernel<<<gather_blocks, 256>>>(cur, rowptr, csr, invdeg, acc16);
        sage_gemm<<<gemm_blocks, 256, SMEM_BYTES>>>(cur, acc16,
                                                    Bt + l * DIM * 2 * DIM,
                                                    bs[l], nxt);
        __half* tmp = cur; cur = nxt; nxt = tmp;
    }

    pool_kernel<<<NG, 512>>>(cur, gids, Wf, bf, out);
}